// round 2
// baseline (speedup 1.0000x reference)
#include <cuda_runtime.h>
#include <mma.h>
#include <cstdint>

using namespace nvcuda;

#define N_TOK 4096
#define DIM   1024
#define NEXP  8
#define HDIM  2048
#define NSLOT (N_TOK * 2)

#define BM 128
#define BN 64
#define BK 16
#define NTHREADS 256
#define LDA 20        // smem row stride (floats) for load tiles
#define LDC 68        // smem row stride for epilogue tile

// ---------------- scratch (device globals; no allocation allowed) ----------
__device__ float g_H[(size_t)NSLOT * HDIM];     // 64 MB: relu(fc1) activations per slot
__device__ int   g_expert_tok[NSLOT];
__device__ float g_expert_w[NSLOT];
__device__ int   g_tok_e[N_TOK * 2];
__device__ float g_tok_w[N_TOK * 2];
__device__ int   g_counts[NEXP];
__device__ int   g_cursor[NEXP];
__device__ int   g_offsets[NEXP + 1];
__device__ float g_colsum[NEXP];
__device__ int   g_top1[NEXP];
__device__ int   g_nt;

// ---------------- cp.async helpers -----------------------------------------
__device__ __forceinline__ void cp_async16(uint32_t dst, const void* src) {
    asm volatile("cp.async.cg.shared.global [%0], [%1], 16;\n" :: "r"(dst), "l"(src));
}
__device__ __forceinline__ void cp_commit() {
    asm volatile("cp.async.commit_group;\n" ::: "memory");
}
template<int N> __device__ __forceinline__ void cp_wait() {
    asm volatile("cp.async.wait_group %0;\n" :: "n"(N) : "memory");
}
__device__ __forceinline__ uint32_t smem_u32(const void* p) {
    return (uint32_t)__cvta_generic_to_shared(p);
}

// ---------------- init ------------------------------------------------------
__global__ void init_kernel() {
    int t = threadIdx.x;
    if (t < NEXP) {
        g_counts[t] = 0;
        g_cursor[t] = 0;
        g_colsum[t] = 0.f;
        g_top1[t]   = 0;
    }
    if (t == 0) g_nt = 0;
}

// ---------------- gate: fp32 logits, softmax, top2, stats ------------------
__global__ void gate_kernel(const float* __restrict__ x,
                            const unsigned char* __restrict__ pm,
                            const float* __restrict__ gw,
                            float* __restrict__ gate_out) {
    int warp = (blockIdx.x * blockDim.x + threadIdx.x) >> 5;
    int lane = threadIdx.x & 31;
    if (warp >= N_TOK) return;
    const int n = warp;
    const float* xr = x + (size_t)n * DIM;

    float acc[NEXP];
#pragma unroll
    for (int e = 0; e < NEXP; e++) acc[e] = 0.f;

    for (int d = lane; d < DIM; d += 32) {
        float xv = xr[d];
#pragma unroll
        for (int e = 0; e < NEXP; e++) acc[e] += xv * gw[e * DIM + d];
    }
#pragma unroll
    for (int e = 0; e < NEXP; e++) {
#pragma unroll
        for (int o = 16; o > 0; o >>= 1)
            acc[e] += __shfl_xor_sync(0xffffffffu, acc[e], o);
    }

    if (lane == 0) {
        bool masked = (pm[n] != 0);
        float m = acc[0];
#pragma unroll
        for (int e = 1; e < NEXP; e++) m = fmaxf(m, acc[e]);
        float gv[NEXP];
        float s = 0.f;
#pragma unroll
        for (int e = 0; e < NEXP; e++) { gv[e] = expf(acc[e] - m); s += gv[e]; }
        float inv = 1.f / s;
#pragma unroll
        for (int e = 0; e < NEXP; e++) {
            gv[e] *= inv;
            if (masked) gv[e] = 0.f;
            gate_out[(size_t)n * NEXP + e] = gv[e];
        }
        int e1 = 0;
#pragma unroll
        for (int e = 1; e < NEXP; e++) if (gv[e] > gv[e1]) e1 = e;
        int e2 = -1;
#pragma unroll
        for (int e = 0; e < NEXP; e++) {
            if (e == e1) continue;
            if (e2 < 0 || gv[e] > gv[e2]) e2 = e;
        }
        float den = gv[e1] + gv[e2];
        if (den == 0.f) den = 1.f;
        float w1 = gv[e1] / den;
        float w2 = gv[e2] / den;

        g_tok_e[2 * n + 0] = e1;
        g_tok_e[2 * n + 1] = e2;
        g_tok_w[2 * n + 0] = w1;
        g_tok_w[2 * n + 1] = w2;

        atomicAdd(&g_counts[e1], 1);
        atomicAdd(&g_counts[e2], 1);
        if (!masked) {
            atomicAdd(&g_top1[e1], 1);
            atomicAdd(&g_nt, 1);
        }
#pragma unroll
        for (int e = 0; e < NEXP; e++) atomicAdd(&g_colsum[e], gv[e]);
    }
}

// ---------------- offsets ---------------------------------------------------
__global__ void offsets_kernel() {
    if (threadIdx.x == 0) {
        int off = 0;
        for (int e = 0; e < NEXP; e++) { g_offsets[e] = off; off += g_counts[e]; }
        g_offsets[NEXP] = off;
    }
}

// ---------------- scatter ---------------------------------------------------
__global__ void scatter_kernel() {
    int n = blockIdx.x * blockDim.x + threadIdx.x;
    if (n >= N_TOK) return;
#pragma unroll
    for (int s = 0; s < 2; s++) {
        int e = g_tok_e[2 * n + s];
        int pos = g_offsets[e] + atomicAdd(&g_cursor[e], 1);
        g_expert_tok[pos] = n;
        g_expert_w[pos]   = g_tok_w[2 * n + s];
    }
}

// Shared helpers for the GEMM mainloop ---------------------------------------
// smem layout (floats): As[2][BM][LDA] then Bs[2][BN][LDA]; total 7680 floats.
// Epilogue overlays Cs[BM][LDC] = 8704 floats over the same buffer.
#define SMEM_FLOATS 8704
#define AS_OFF(b)  ((b) * (BM * LDA))
#define BS_OFF(b)  (2 * (BM * LDA) + (b) * (BN * LDA))

template<typename FragA, typename FragB>
__device__ __forceinline__ void tf32_round(FragA& a) {
#pragma unroll
    for (int i = 0; i < a.num_elements; i++) a.x[i] = wmma::__float_to_tf32(a.x[i]);
}

// ---------------- grouped GEMM1: g_H = relu(Xg @ W1^T + b1) -----------------
__global__ __launch_bounds__(NTHREADS) void gemm1_kernel(
        const float* __restrict__ x,
        const float* __restrict__ w1,
        const float* __restrict__ b1) {
    const int e = blockIdx.z;
    const int off = g_offsets[e];
    const int cnt = g_offsets[e + 1] - off;
    const int row0 = blockIdx.y * BM;
    if (row0 >= cnt) return;
    const int h0 = blockIdx.x * BN;

    __shared__ __align__(16) float smem[SMEM_FLOATS];

    const int tid  = threadIdx.x;
    const int warp = tid >> 5;
    const int wm   = warp >> 1;   // 0..3 -> 32-row strip
    const int wn   = warp & 1;    // 0..1 -> 32-col strip

    // per-thread source pointers (rows fixed across K loop)
    const float* a_src[2];
    int a_row[2], a_col[2];
#pragma unroll
    for (int i = 0; i < 2; i++) {
        int c = tid + i * NTHREADS;          // 0..511
        int r = c >> 2;                      // 0..127
        int c4 = (c & 3) * 4;
        int gr = row0 + r; if (gr >= cnt) gr = cnt - 1;
        int tok = g_expert_tok[off + gr];
        a_src[i] = x + (size_t)tok * DIM + c4;
        a_row[i] = r; a_col[i] = c4;
    }
    const int bR = tid >> 2;
    const int bC = (tid & 3) * 4;
    const float* b_src = w1 + ((size_t)(e * HDIM + h0 + bR)) * DIM + bC;

    wmma::fragment<wmma::accumulator, 16, 16, 8, float> acc[2][2];
#pragma unroll
    for (int i = 0; i < 2; i++)
#pragma unroll
        for (int j = 0; j < 2; j++) wmma::fill_fragment(acc[i][j], 0.f);

    const int T = DIM / BK;   // 64

    // prefetch tile 0 into buffer 0
    {
#pragma unroll
        for (int i = 0; i < 2; i++)
            cp_async16(smem_u32(&smem[AS_OFF(0) + a_row[i] * LDA + a_col[i]]), a_src[i]);
        cp_async16(smem_u32(&smem[BS_OFF(0) + bR * LDA + bC]), b_src);
        cp_commit();
    }

    for (int t = 0; t < T; t++) {
        int b = t & 1;
        if (t + 1 < T) {
            int nb = (t + 1) & 1;
#pragma unroll
            for (int i = 0; i < 2; i++)
                cp_async16(smem_u32(&smem[AS_OFF(nb) + a_row[i] * LDA + a_col[i]]),
                           a_src[i] + (t + 1) * BK);
            cp_async16(smem_u32(&smem[BS_OFF(nb) + bR * LDA + bC]), b_src + (t + 1) * BK);
            cp_commit();
            cp_wait<1>();
        } else {
            cp_wait<0>();
        }
        __syncthreads();

#pragma unroll
        for (int kk = 0; kk < BK; kk += 8) {
            wmma::fragment<wmma::matrix_a, 16, 16, 8, wmma::precision::tf32, wmma::row_major> a[2];
            wmma::fragment<wmma::matrix_b, 16, 16, 8, wmma::precision::tf32, wmma::col_major> bb[2];
            wmma::load_matrix_sync(a[0], &smem[AS_OFF(b) + (wm * 32 + 0)  * LDA + kk], LDA);
            wmma::load_matrix_sync(a[1], &smem[AS_OFF(b) + (wm * 32 + 16) * LDA + kk], LDA);
            wmma::load_matrix_sync(bb[0], &smem[BS_OFF(b) + (wn * 32 + 0)  * LDA + kk], LDA);
            wmma::load_matrix_sync(bb[1], &smem[BS_OFF(b) + (wn * 32 + 16) * LDA + kk], LDA);
#pragma unroll
            for (int i = 0; i < 2; i++) tf32_round<decltype(a[0]), decltype(bb[0])>(a[i]);
#pragma unroll
            for (int j = 0; j < 2; j++) tf32_round<decltype(bb[0]), decltype(bb[0])>(bb[j]);
#pragma unroll
            for (int i = 0; i < 2; i++)
#pragma unroll
                for (int j = 0; j < 2; j++)
                    wmma::mma_sync(acc[i][j], a[i], bb[j], acc[i][j]);
        }
        __syncthreads();
    }

    // epilogue: stage to smem, bias + relu, vectorized store to g_H
#pragma unroll
    for (int i = 0; i < 2; i++)
#pragma unroll
        for (int j = 0; j < 2; j++)
            wmma::store_matrix_sync(&smem[(wm * 32 + i * 16) * LDC + (wn * 32 + j * 16)],
                                    acc[i][j], LDC, wmma::mem_row_major);
    __syncthreads();

#pragma unroll
    for (int i = 0; i < 8; i++) {
        int idx4 = tid + i * NTHREADS;   // 0..2047 float4s
        int r  = idx4 >> 4;
        int c4 = (idx4 & 15) * 4;
        if (row0 + r < cnt) {
            int h = h0 + c4;
            float4 v = *(const float4*)&smem[r * LDC + c4];
            const float4 bv = *(const float4*)&b1[e * HDIM + h];
            v.x = fmaxf(v.x + bv.x, 0.f);
            v.y = fmaxf(v.y + bv.y, 0.f);
            v.z = fmaxf(v.z + bv.z, 0.f);
            v.w = fmaxf(v.w + bv.w, 0.f);
            *(float4*)&g_H[(size_t)(off + row0 + r) * HDIM + h] = v;
        }
    }
}

// ---------------- grouped GEMM2: out += w * (g_H @ W2^T + b2) ---------------
__global__ __launch_bounds__(NTHREADS) void gemm2_kernel(
        const float* __restrict__ w2,
        const float* __restrict__ b2,
        float* __restrict__ out) {
    const int e = blockIdx.z;
    const int off = g_offsets[e];
    const int cnt = g_offsets[e + 1] - off;
    const int row0 = blockIdx.y * BM;
    if (row0 >= cnt) return;
    const int d0 = blockIdx.x * BN;

    __shared__ __align__(16) float smem[SMEM_FLOATS];

    const int tid  = threadIdx.x;
    const int warp = tid >> 5;
    const int wm   = warp >> 1;
    const int wn   = warp & 1;

    const float* a_src[2];
    int a_row[2], a_col[2];
#pragma unroll
    for (int i = 0; i < 2; i++) {
        int c = tid + i * NTHREADS;
        int r = c >> 2;
        int c4 = (c & 3) * 4;
        int gr = row0 + r; if (gr >= cnt) gr = cnt - 1;
        a_src[i] = g_H + (size_t)(off + gr) * HDIM + c4;
        a_row[i] = r; a_col[i] = c4;
    }
    const int bR = tid >> 2;
    const int bC = (tid & 3) * 4;
    const float* b_src = w2 + ((size_t)(e * DIM + d0 + bR)) * HDIM + bC;

    wmma::fragment<wmma::accumulator, 16, 16, 8, float> acc[2][2];
#pragma unroll
    for (int i = 0; i < 2; i++)
#pragma unroll
        for (int j = 0; j < 2; j++) wmma::fill_fragment(acc[i][j], 0.f);

    const int T = HDIM / BK;  // 128

    {
#pragma unroll
        for (int i = 0; i < 2; i++)
            cp_async16(smem_u32(&smem[AS_OFF(0) + a_row[i] * LDA + a_col[i]]), a_src[i]);
        cp_async16(smem_u32(&smem[BS_OFF(0) + bR * LDA + bC]), b_src);
        cp_commit();
    }

    for (int t = 0; t < T; t++) {
        int b = t & 1;
        if (t + 1 < T) {
            int nb = (t + 1) & 1;
#pragma unroll
            for (int i = 0; i < 2; i++)
                cp_async16(smem_u32(&smem[AS_OFF(nb) + a_row[i] * LDA + a_col[i]]),
                           a_src[i] + (t + 1) * BK);
            cp_async16(smem_u32(&smem[BS_OFF(nb) + bR * LDA + bC]), b_src + (t + 1) * BK);
            cp_commit();
            cp_wait<1>();
        } else {
            cp_wait<0>();
        }
        __syncthreads();

#pragma unroll
        for (int kk = 0; kk < BK; kk += 8) {
            wmma::fragment<wmma::matrix_a, 16, 16, 8, wmma::precision::tf32, wmma::row_major> a[2];
            wmma::fragment<wmma::matrix_b, 16, 16, 8, wmma::precision::tf32, wmma::col_major> bb[2];
            wmma::load_matrix_sync(a[0], &smem[AS_OFF(b) + (wm * 32 + 0)  * LDA + kk], LDA);
            wmma::load_matrix_sync(a[1], &smem[AS_OFF(b) + (wm * 32 + 16) * LDA + kk], LDA);
            wmma::load_matrix_sync(bb[0], &smem[BS_OFF(b) + (wn * 32 + 0)  * LDA + kk], LDA);
            wmma::load_matrix_sync(bb[1], &smem[BS_OFF(b) + (wn * 32 + 16) * LDA + kk], LDA);
#pragma unroll
            for (int i = 0; i < 2; i++) tf32_round<decltype(a[0]), decltype(bb[0])>(a[i]);
#pragma unroll
            for (int j = 0; j < 2; j++) tf32_round<decltype(bb[0]), decltype(bb[0])>(bb[j]);
#pragma unroll
            for (int i = 0; i < 2; i++)
#pragma unroll
                for (int j = 0; j < 2; j++)
                    wmma::mma_sync(acc[i][j], a[i], bb[j], acc[i][j]);
        }
        __syncthreads();
    }

#pragma unroll
    for (int i = 0; i < 2; i++)
#pragma unroll
        for (int j = 0; j < 2; j++)
            wmma::store_matrix_sync(&smem[(wm * 32 + i * 16) * LDC + (wn * 32 + j * 16)],
                                    acc[i][j], LDC, wmma::mem_row_major);
    __syncthreads();

#pragma unroll
    for (int i = 0; i < 8; i++) {
        int idx4 = tid + i * NTHREADS;
        int r  = idx4 >> 4;
        int c4 = (idx4 & 15) * 4;
        if (row0 + r < cnt) {
            int slot = off + row0 + r;
            int tok  = g_expert_tok[slot];
            float w  = g_expert_w[slot];
            int d = d0 + c4;
            float4 v = *(const float4*)&smem[r * LDC + c4];
            const float4 bv = *(const float4*)&b2[e * DIM + d];
            float* o = &out[(size_t)tok * DIM + d];
            atomicAdd(o + 0, (v.x + bv.x) * w);
            atomicAdd(o + 1, (v.y + bv.y) * w);
            atomicAdd(o + 2, (v.z + bv.z) * w);
            atomicAdd(o + 3, (v.w + bv.w) * w);
        }
    }
}

// ---------------- lb_loss ---------------------------------------------------
__global__ void loss_kernel(float* __restrict__ loss_out) {
    if (threadIdx.x == 0) {
        float nt = (float)g_nt;
        float s = 0.f;
        for (int e = 0; e < NEXP; e++)
            s += ((float)g_top1[e] / nt) * (g_colsum[e] / nt);
        *loss_out = (float)NEXP * s;
    }
}

// ---------------- launch -----------------------------------------------------
extern "C" void kernel_launch(void* const* d_in, const int* in_sizes, int n_in,
                              void* d_out, int out_size) {
    const float*         x      = (const float*)d_in[0];
    const unsigned char* pm     = (const unsigned char*)d_in[1];
    const float*         gate_w = (const float*)d_in[2];
    const float*         fc1_w  = (const float*)d_in[3];
    const float*         fc1_b  = (const float*)d_in[4];
    const float*         fc2_w  = (const float*)d_in[5];
    const float*         fc2_b  = (const float*)d_in[6];
    (void)in_sizes; (void)n_in; (void)out_size;

    float* out      = (float*)d_out;
    float* gate_out = out + (size_t)N_TOK * DIM;
    float* loss_out = gate_out + (size_t)N_TOK * NEXP;

    cudaMemsetAsync(out, 0, (size_t)N_TOK * DIM * sizeof(float));
    init_kernel<<<1, 32>>>();
    gate_kernel<<<N_TOK / 8, 256>>>(x, pm, gate_w, gate_out);
    offsets_kernel<<<1, 32>>>();
    scatter_kernel<<<N_TOK / 256, 256>>>();
    gemm1_kernel<<<dim3(HDIM / BN, N_TOK / BM, NEXP), NTHREADS>>>(x, fc1_w, fc1_b);
    gemm2_kernel<<<dim3(DIM / BN, N_TOK / BM, NEXP), NTHREADS>>>(fc2_w, fc2_b, out);
    loss_kernel<<<1, 32>>>(loss_out);
}

// round 4
// speedup vs baseline: 1.1837x; 1.1837x over previous
#include <cuda_runtime.h>
#include <mma.h>
#include <cstdint>

using namespace nvcuda;

#define N_TOK 4096
#define DIM   1024
#define NEXP  8
#define HDIM  2048
#define NSLOT 8192
#define PAD   128

#define TM 128
#define TN 64
#define BK 16
#define NT 128            // threads per gemm block (4 warps)
#define LDS_A 20          // smem row stride (floats)
#define LDS_C 68

// smem float offsets: As[2][128][20] | Bs[2][64][20]; epilogue overlays Cs[128][68]
#define AS_F(b) ((b) * (TM * LDS_A))
#define BS_F(b) (2 * (TM * LDS_A) + (b) * (TN * LDS_A))
#define SMEM_BYTES (TM * LDS_C * 4)   // 34816 (>= mainloop 30720)

// ---------------- scratch (device globals) ----------------------------------
__device__ __align__(256) float g_Xg[(size_t)(NSLOT + PAD) * DIM];   // gathered, tf32-rounded
__device__ __align__(256) float g_H [(size_t)(NSLOT + PAD) * HDIM];  // relu out, tf32-rounded
__device__ __align__(256) float g_w1r[(size_t)NEXP * HDIM * DIM];
__device__ __align__(256) float g_w2r[(size_t)NEXP * DIM * HDIM];
__device__ int   g_expert_tok[NSLOT];
__device__ float g_expert_w[NSLOT];
__device__ int   g_tok_e[N_TOK * 2];
__device__ float g_tok_w[N_TOK * 2];
__device__ int   g_counts[NEXP];
__device__ int   g_cursor[NEXP];
__device__ int   g_offsets[NEXP + 1];
__device__ float g_colsum[NEXP];
__device__ int   g_top1[NEXP];
__device__ int   g_nt;

// ---------------- helpers ---------------------------------------------------
__device__ __forceinline__ uint32_t smem_u32(const void* p) {
    return (uint32_t)__cvta_generic_to_shared(p);
}
__device__ __forceinline__ void cp_async16(uint32_t dst, const void* src) {
    asm volatile("cp.async.cg.shared.global [%0], [%1], 16;\n" :: "r"(dst), "l"(src));
}
__device__ __forceinline__ void cp_commit() {
    asm volatile("cp.async.commit_group;\n" ::: "memory");
}
template<int N> __device__ __forceinline__ void cp_wait() {
    asm volatile("cp.async.wait_group %0;\n" :: "n"(N) : "memory");
}
__device__ __forceinline__ float tf32r(float x) {
    uint32_t u;
    asm("cvt.rna.tf32.f32 %0, %1;" : "=r"(u) : "f"(x));
    return __uint_as_float(u);
}

// ---------------- init / gate / offsets / scatter (proven) ------------------
__global__ void init_kernel() {
    int t = threadIdx.x;
    if (t < NEXP) { g_counts[t] = 0; g_cursor[t] = 0; g_colsum[t] = 0.f; g_top1[t] = 0; }
    if (t == 0) g_nt = 0;
}

__global__ void gate_kernel(const float* __restrict__ x,
                            const unsigned char* __restrict__ pm,
                            const float* __restrict__ gw,
                            float* __restrict__ gate_out) {
    int warp = (blockIdx.x * blockDim.x + threadIdx.x) >> 5;
    int lane = threadIdx.x & 31;
    if (warp >= N_TOK) return;
    const int n = warp;
    const float* xr = x + (size_t)n * DIM;

    float acc[NEXP];
#pragma unroll
    for (int e = 0; e < NEXP; e++) acc[e] = 0.f;
    for (int d = lane; d < DIM; d += 32) {
        float xv = xr[d];
#pragma unroll
        for (int e = 0; e < NEXP; e++) acc[e] += xv * gw[e * DIM + d];
    }
#pragma unroll
    for (int e = 0; e < NEXP; e++) {
#pragma unroll
        for (int o = 16; o > 0; o >>= 1)
            acc[e] += __shfl_xor_sync(0xffffffffu, acc[e], o);
    }
    if (lane == 0) {
        bool masked = (pm[n] != 0);
        float m = acc[0];
#pragma unroll
        for (int e = 1; e < NEXP; e++) m = fmaxf(m, acc[e]);
        float gv[NEXP]; float s = 0.f;
#pragma unroll
        for (int e = 0; e < NEXP; e++) { gv[e] = expf(acc[e] - m); s += gv[e]; }
        float inv = 1.f / s;
#pragma unroll
        for (int e = 0; e < NEXP; e++) {
            gv[e] *= inv;
            if (masked) gv[e] = 0.f;
            gate_out[(size_t)n * NEXP + e] = gv[e];
        }
        int e1 = 0;
#pragma unroll
        for (int e = 1; e < NEXP; e++) if (gv[e] > gv[e1]) e1 = e;
        int e2 = -1;
#pragma unroll
        for (int e = 0; e < NEXP; e++) {
            if (e == e1) continue;
            if (e2 < 0 || gv[e] > gv[e2]) e2 = e;
        }
        float den = gv[e1] + gv[e2];
        if (den == 0.f) den = 1.f;
        g_tok_e[2 * n + 0] = e1;
        g_tok_e[2 * n + 1] = e2;
        g_tok_w[2 * n + 0] = gv[e1] / den;
        g_tok_w[2 * n + 1] = gv[e2] / den;
        atomicAdd(&g_counts[e1], 1);
        atomicAdd(&g_counts[e2], 1);
        if (!masked) { atomicAdd(&g_top1[e1], 1); atomicAdd(&g_nt, 1); }
#pragma unroll
        for (int e = 0; e < NEXP; e++) atomicAdd(&g_colsum[e], gv[e]);
    }
}

__global__ void offsets_kernel() {
    if (threadIdx.x == 0) {
        int off = 0;
        for (int e = 0; e < NEXP; e++) { g_offsets[e] = off; off += g_counts[e]; }
        g_offsets[NEXP] = off;
    }
}

__global__ void scatter_kernel() {
    int n = blockIdx.x * blockDim.x + threadIdx.x;
    if (n >= N_TOK) return;
#pragma unroll
    for (int s = 0; s < 2; s++) {
        int e = g_tok_e[2 * n + s];
        int pos = g_offsets[e] + atomicAdd(&g_cursor[e], 1);
        g_expert_tok[pos] = n;
        g_expert_w[pos]   = g_tok_w[2 * n + s];
    }
}

// ---------------- gather (+ tf32 pre-round) ---------------------------------
__global__ void gather_kernel(const float* __restrict__ x) {
    int s = blockIdx.x;
    int tok = g_expert_tok[s];
    const float4* src = (const float4*)(x + (size_t)tok * DIM);
    float4* dst = (float4*)(g_Xg + (size_t)s * DIM);
    int c = threadIdx.x;                  // 256 threads -> 256 float4 = 1024 floats
    float4 v = src[c];
    v.x = tf32r(v.x); v.y = tf32r(v.y); v.z = tf32r(v.z); v.w = tf32r(v.w);
    dst[c] = v;
}

template<int WHICH>
__global__ void round_w_kernel(const float4* __restrict__ src, int n4) {
    float4* dst = (float4*)(WHICH == 0 ? g_w1r : g_w2r);
    int stride = gridDim.x * blockDim.x;
    for (int i = blockIdx.x * blockDim.x + threadIdx.x; i < n4; i += stride) {
        float4 v = src[i];
        v.x = tf32r(v.x); v.y = tf32r(v.y); v.z = tf32r(v.z); v.w = tf32r(v.w);
        dst[i] = v;
    }
}

// ---------------- grouped GEMM (wmma tf32, zero in-loop conversions) --------
// MODE 0: g_H = tf32r(relu(Xg @ w1r^T + b1))   KTOT=DIM,  NCOLS=HDIM
// MODE 1: out[tok] += w * (g_H @ w2r^T + b2)   KTOT=HDIM, NCOLS=DIM
template<int KTOT, int MODE>
__global__ __launch_bounds__(NT, 2) void gemm_kernel(const float* __restrict__ bias,
                                                     float* __restrict__ outp) {
    const int e = blockIdx.z;
    const int off = g_offsets[e];
    const int cnt = g_offsets[e + 1] - off;
    const int row0 = blockIdx.y * TM;
    if (row0 >= cnt) return;
    const int n0 = blockIdx.x * TN;
    const int NCOLS = (MODE == 0) ? HDIM : DIM;

    extern __shared__ __align__(16) float smem[];

    const int tid  = threadIdx.x;
    const int warp = tid >> 5;           // 0..3, owns 32-row strip

    const float* Abase = (MODE == 0) ? g_Xg : g_H;
    const float* Bbase = (MODE == 0) ? g_w1r : g_w2r;

    // cp.async per-thread slots: A = 512 float4, B = 256 float4 per stage
    const float* a_src[4];
    uint32_t a_dst[4];
#pragma unroll
    for (int i = 0; i < 4; i++) {
        int cid = tid + i * NT;          // 0..511
        int r   = cid >> 2;
        int c4  = (cid & 3) * 4;
        a_src[i] = Abase + (size_t)(off + row0 + r) * KTOT + c4;
        a_dst[i] = smem_u32(&smem[AS_F(0) + r * LDS_A + c4]);
    }
    const float* b_src[2];
    uint32_t b_dst[2];
#pragma unroll
    for (int i = 0; i < 2; i++) {
        int cid = tid + i * NT;          // 0..255
        int r   = cid >> 2;
        int c4  = (cid & 3) * 4;
        b_src[i] = Bbase + (size_t)(e * NCOLS + n0 + r) * KTOT + c4;
        b_dst[i] = smem_u32(&smem[BS_F(0) + r * LDS_A + c4]);
    }
    const uint32_t A_FLIP = TM * LDS_A * 4;   // bytes between A buffers
    const uint32_t B_FLIP = TN * LDS_A * 4;

    wmma::fragment<wmma::accumulator, 16, 16, 8, float> acc[2][4];
#pragma unroll
    for (int i = 0; i < 2; i++)
#pragma unroll
        for (int j = 0; j < 4; j++) wmma::fill_fragment(acc[i][j], 0.f);

    const int T = KTOT / BK;

    // prefetch stage 0 -> buffer 0
#pragma unroll
    for (int i = 0; i < 4; i++) cp_async16(a_dst[i], a_src[i]);
#pragma unroll
    for (int i = 0; i < 2; i++) cp_async16(b_dst[i], b_src[i]);
    cp_commit();

    for (int t = 0; t < T; t++) {
        const int b = t & 1;
        if (t + 1 < T) {
            const uint32_t fa = (b ^ 1) ? A_FLIP : 0u;
            const uint32_t fb = (b ^ 1) ? B_FLIP : 0u;
#pragma unroll
            for (int i = 0; i < 4; i++)
                cp_async16(a_dst[i] + fa, a_src[i] + (size_t)(t + 1) * BK);
#pragma unroll
            for (int i = 0; i < 2; i++)
                cp_async16(b_dst[i] + fb, b_src[i] + (size_t)(t + 1) * BK);
            cp_commit();
            cp_wait<1>();
        } else {
            cp_wait<0>();
        }
        __syncthreads();

#pragma unroll
        for (int kk = 0; kk < BK; kk += 8) {
            wmma::fragment<wmma::matrix_a, 16, 16, 8, wmma::precision::tf32, wmma::row_major> af[2];
            wmma::fragment<wmma::matrix_b, 16, 16, 8, wmma::precision::tf32, wmma::col_major> bf[4];
            wmma::load_matrix_sync(af[0], &smem[AS_F(b) + (warp * 32 + 0)  * LDS_A + kk], LDS_A);
            wmma::load_matrix_sync(af[1], &smem[AS_F(b) + (warp * 32 + 16) * LDS_A + kk], LDS_A);
#pragma unroll
            for (int j = 0; j < 4; j++)
                wmma::load_matrix_sync(bf[j], &smem[BS_F(b) + (j * 16) * LDS_A + kk], LDS_A);
#pragma unroll
            for (int i = 0; i < 2; i++)
#pragma unroll
                for (int j = 0; j < 4; j++)
                    wmma::mma_sync(acc[i][j], af[i], bf[j], acc[i][j]);
        }
        __syncthreads();
    }

    // epilogue: stage 128x64 into Cs (overlays load buffers; loop's trailing sync done)
#pragma unroll
    for (int i = 0; i < 2; i++)
#pragma unroll
        for (int j = 0; j < 4; j++)
            wmma::store_matrix_sync(&smem[(warp * 32 + i * 16) * LDS_C + j * 16],
                                    acc[i][j], LDS_C, wmma::mem_row_major);
    __syncthreads();

#pragma unroll
    for (int i = 0; i < 16; i++) {
        int idx4 = tid + i * NT;             // 0..2047 float4
        int r    = idx4 >> 4;
        int c4   = (idx4 & 15) * 4;
        if (row0 + r < cnt) {
            int slot = off + row0 + r;
            float4 v = *(const float4*)&smem[r * LDS_C + c4];
            const float4 bv = *(const float4*)&bias[e * NCOLS + n0 + c4];
            if (MODE == 0) {
                v.x = tf32r(fmaxf(v.x + bv.x, 0.f));
                v.y = tf32r(fmaxf(v.y + bv.y, 0.f));
                v.z = tf32r(fmaxf(v.z + bv.z, 0.f));
                v.w = tf32r(fmaxf(v.w + bv.w, 0.f));
                *(float4*)&g_H[(size_t)slot * HDIM + n0 + c4] = v;
            } else {
                int tok = g_expert_tok[slot];
                float w = g_expert_w[slot];
                float* o = &outp[(size_t)tok * DIM + n0 + c4];
                atomicAdd(o + 0, (v.x + bv.x) * w);
                atomicAdd(o + 1, (v.y + bv.y) * w);
                atomicAdd(o + 2, (v.z + bv.z) * w);
                atomicAdd(o + 3, (v.w + bv.w) * w);
            }
        }
    }
}

// ---------------- lb_loss ---------------------------------------------------
__global__ void loss_kernel(float* __restrict__ loss_out) {
    if (threadIdx.x == 0) {
        float nt = (float)g_nt;
        float s = 0.f;
        for (int e = 0; e < NEXP; e++)
            s += ((float)g_top1[e] / nt) * (g_colsum[e] / nt);
        *loss_out = (float)NEXP * s;
    }
}

// ---------------- launch -----------------------------------------------------
extern "C" void kernel_launch(void* const* d_in, const int* in_sizes, int n_in,
                              void* d_out, int out_size) {
    const float*         x      = (const float*)d_in[0];
    const unsigned char* pm     = (const unsigned char*)d_in[1];
    const float*         gate_w = (const float*)d_in[2];
    const float*         fc1_w  = (const float*)d_in[3];
    const float*         fc1_b  = (const float*)d_in[4];
    const float*         fc2_w  = (const float*)d_in[5];
    const float*         fc2_b  = (const float*)d_in[6];
    (void)in_sizes; (void)n_in; (void)out_size;

    float* out      = (float*)d_out;
    float* gate_out = out + (size_t)N_TOK * DIM;
    float* loss_out = gate_out + (size_t)N_TOK * NEXP;

    cudaFuncSetAttribute(gemm_kernel<DIM, 0>,
                         cudaFuncAttributeMaxDynamicSharedMemorySize, SMEM_BYTES);
    cudaFuncSetAttribute(gemm_kernel<HDIM, 1>,
                         cudaFuncAttributeMaxDynamicSharedMemorySize, SMEM_BYTES);

    cudaMemsetAsync(out, 0, (size_t)N_TOK * DIM * sizeof(float));
    init_kernel<<<1, 32>>>();
    gate_kernel<<<N_TOK / 8, 256>>>(x, pm, gate_w, gate_out);
    offsets_kernel<<<1, 32>>>();
    scatter_kernel<<<N_TOK / 256, 256>>>();
    gather_kernel<<<NSLOT, 256>>>(x);
    round_w_kernel<0><<<2048, 256>>>((const float4*)fc1_w, NEXP * HDIM * DIM / 4);
    round_w_kernel<1><<<2048, 256>>>((const float4*)fc2_w, NEXP * DIM * HDIM / 4);
    gemm_kernel<DIM, 0><<<dim3(HDIM / TN, NSLOT / TM, NEXP), NT, SMEM_BYTES>>>(fc1_b, nullptr);
    gemm_kernel<HDIM, 1><<<dim3(DIM / TN, NSLOT / TM, NEXP), NT, SMEM_BYTES>>>(fc2_b, out);
    loss_kernel<<<1, 32>>>(loss_out);
}

// round 5
// speedup vs baseline: 2.5416x; 2.1472x over previous
#include <cuda_runtime.h>
#include <cuda_fp16.h>
#include <mma.h>
#include <cstdint>

using namespace nvcuda;

#define N_TOK 4096
#define DIM   1024
#define NEXP  8
#define HDIM  2048
#define NSLOT 8192
#define PAD   128

// gemm tiling (fp16 wmma m16n16k16)
#define TM 128
#define TN 128
#define BK 32
#define NTH 256           // 8 warps: 4 (M) x 2 (N), warp tile 32x64
#define LDB 40            // smem row stride in halves (80B -> conflict-free LDSM)
#define LDC 68            // epilogue fp32 row stride

#define ASZ (TM * LDB)            // halves per A stage (5120)
#define AS_H(b) ((b) * ASZ)
#define BS_H(b) (2 * ASZ + (b) * ASZ)
#define SMEM_BYTES (4 * ASZ * 2)  // 40960B (mainloop); epilogue overlay 34816B fits

// ---------------- scratch (device globals) ----------------------------------
__device__ __align__(256) __half g_Xg[(size_t)(NSLOT + PAD) * DIM];
__device__ __align__(256) __half g_H [(size_t)(NSLOT + PAD) * HDIM];
__device__ __align__(256) __half g_w1h[(size_t)NEXP * HDIM * DIM];
__device__ __align__(256) __half g_w2h[(size_t)NEXP * DIM * HDIM];
__device__ int   g_expert_tok[NSLOT];
__device__ float g_expert_w[NSLOT];
__device__ int   g_tok_e[N_TOK * 2];
__device__ float g_tok_w[N_TOK * 2];
__device__ int   g_counts[NEXP];
__device__ int   g_cursor[NEXP];
__device__ int   g_offsets[NEXP + 1];
__device__ float g_colsum[NEXP];
__device__ int   g_top1[NEXP];
__device__ int   g_nt;

// ---------------- helpers ---------------------------------------------------
__device__ __forceinline__ uint32_t smem_u32(const void* p) {
    return (uint32_t)__cvta_generic_to_shared(p);
}
__device__ __forceinline__ void cp_async16(uint32_t dst, const void* src) {
    asm volatile("cp.async.cg.shared.global [%0], [%1], 16;\n" :: "r"(dst), "l"(src));
}
__device__ __forceinline__ void cp_commit() {
    asm volatile("cp.async.commit_group;\n" ::: "memory");
}
template<int N> __device__ __forceinline__ void cp_wait() {
    asm volatile("cp.async.wait_group %0;\n" :: "n"(N) : "memory");
}

// ---------------- init / gate / offsets / scatter (proven) ------------------
__global__ void init_kernel() {
    int t = threadIdx.x;
    if (t < NEXP) { g_counts[t] = 0; g_cursor[t] = 0; g_colsum[t] = 0.f; g_top1[t] = 0; }
    if (t == 0) g_nt = 0;
}

__global__ void gate_kernel(const float* __restrict__ x,
                            const unsigned char* __restrict__ pm,
                            const float* __restrict__ gw,
                            float* __restrict__ gate_out) {
    int warp = (blockIdx.x * blockDim.x + threadIdx.x) >> 5;
    int lane = threadIdx.x & 31;
    if (warp >= N_TOK) return;
    const int n = warp;
    const float* xr = x + (size_t)n * DIM;

    float acc[NEXP];
#pragma unroll
    for (int e = 0; e < NEXP; e++) acc[e] = 0.f;
    for (int d = lane; d < DIM; d += 32) {
        float xv = xr[d];
#pragma unroll
        for (int e = 0; e < NEXP; e++) acc[e] += xv * gw[e * DIM + d];
    }
#pragma unroll
    for (int e = 0; e < NEXP; e++) {
#pragma unroll
        for (int o = 16; o > 0; o >>= 1)
            acc[e] += __shfl_xor_sync(0xffffffffu, acc[e], o);
    }
    if (lane == 0) {
        bool masked = (pm[n] != 0);
        float m = acc[0];
#pragma unroll
        for (int e = 1; e < NEXP; e++) m = fmaxf(m, acc[e]);
        float gv[NEXP]; float s = 0.f;
#pragma unroll
        for (int e = 0; e < NEXP; e++) { gv[e] = expf(acc[e] - m); s += gv[e]; }
        float inv = 1.f / s;
#pragma unroll
        for (int e = 0; e < NEXP; e++) {
            gv[e] *= inv;
            if (masked) gv[e] = 0.f;
            gate_out[(size_t)n * NEXP + e] = gv[e];
        }
        int e1 = 0;
#pragma unroll
        for (int e = 1; e < NEXP; e++) if (gv[e] > gv[e1]) e1 = e;
        int e2 = -1;
#pragma unroll
        for (int e = 0; e < NEXP; e++) {
            if (e == e1) continue;
            if (e2 < 0 || gv[e] > gv[e2]) e2 = e;
        }
        float den = gv[e1] + gv[e2];
        if (den == 0.f) den = 1.f;
        g_tok_e[2 * n + 0] = e1;
        g_tok_e[2 * n + 1] = e2;
        g_tok_w[2 * n + 0] = gv[e1] / den;
        g_tok_w[2 * n + 1] = gv[e2] / den;
        atomicAdd(&g_counts[e1], 1);
        atomicAdd(&g_counts[e2], 1);
        if (!masked) { atomicAdd(&g_top1[e1], 1); atomicAdd(&g_nt, 1); }
#pragma unroll
        for (int e = 0; e < NEXP; e++) atomicAdd(&g_colsum[e], gv[e]);
    }
}

__global__ void offsets_kernel() {
    if (threadIdx.x == 0) {
        int off = 0;
        for (int e = 0; e < NEXP; e++) { g_offsets[e] = off; off += g_counts[e]; }
        g_offsets[NEXP] = off;
    }
}

__global__ void scatter_kernel() {
    int n = blockIdx.x * blockDim.x + threadIdx.x;
    if (n >= N_TOK) return;
#pragma unroll
    for (int s = 0; s < 2; s++) {
        int e = g_tok_e[2 * n + s];
        int pos = g_offsets[e] + atomicAdd(&g_cursor[e], 1);
        g_expert_tok[pos] = n;
        g_expert_w[pos]   = g_tok_w[2 * n + s];
    }
}

// ---------------- gather (fp32 -> fp16 rows of X) ---------------------------
__global__ void gather_kernel(const float* __restrict__ x) {
    int s = blockIdx.x;
    int tok = g_expert_tok[s];
    const float4* src = (const float4*)(x + (size_t)tok * DIM);
    uint2* dst = (uint2*)(g_Xg + (size_t)s * DIM);
    int c = threadIdx.x;                  // 256 threads x 4 floats
    float4 v = src[c];
    __half2 h0 = __floats2half2_rn(v.x, v.y);
    __half2 h1 = __floats2half2_rn(v.z, v.w);
    uint2 o;
    o.x = *(uint32_t*)&h0;
    o.y = *(uint32_t*)&h1;
    dst[c] = o;
}

template<int WHICH>
__global__ void conv_w_kernel(const float4* __restrict__ src, int n4) {
    uint2* dst = (uint2*)(WHICH == 0 ? g_w1h : g_w2h);
    int stride = gridDim.x * blockDim.x;
    for (int i = blockIdx.x * blockDim.x + threadIdx.x; i < n4; i += stride) {
        float4 v = src[i];
        __half2 h0 = __floats2half2_rn(v.x, v.y);
        __half2 h1 = __floats2half2_rn(v.z, v.w);
        uint2 o;
        o.x = *(uint32_t*)&h0;
        o.y = *(uint32_t*)&h1;
        dst[i] = o;
    }
}

// ---------------- grouped GEMM (fp16 wmma, fp32 accumulate) -----------------
// MODE 0: g_H = half(relu(Xg @ w1h^T + b1))    KTOT=DIM,  NCOLS=HDIM
// MODE 1: out[tok] += w * (g_H @ w2h^T + b2)   KTOT=HDIM, NCOLS=DIM
template<int KTOT, int MODE>
__global__ __launch_bounds__(NTH, 1) void gemm_kernel(const float* __restrict__ bias,
                                                      float* __restrict__ outp) {
    const int e = blockIdx.z;
    const int off = g_offsets[e];
    const int cnt = g_offsets[e + 1] - off;
    const int row0 = blockIdx.y * TM;
    if (row0 >= cnt) return;
    const int n0 = blockIdx.x * TN;
    const int NCOLS = (MODE == 0) ? HDIM : DIM;

    extern __shared__ __align__(16) __half sh[];

    const int tid  = threadIdx.x;
    const int warp = tid >> 5;
    const int wm   = warp >> 1;          // 0..3 : 32-row strip
    const int wn   = warp & 1;           // 0..1 : 64-col strip

    const __half* Abase = (MODE == 0) ? g_Xg : g_H;
    const __half* Bbase = (MODE == 0) ? g_w1h : g_w2h;

    // cp.async: per stage A = 512 chunks(16B), B = 512 chunks; 2+2 per thread
    const __half* a_src[2];
    uint32_t a_dst[2];
    const __half* b_src[2];
    uint32_t b_dst[2];
#pragma unroll
    for (int i = 0; i < 2; i++) {
        int cid = tid + i * NTH;         // 0..511
        int r   = cid >> 2;              // 0..127
        int c8  = (cid & 3) * 8;         // halves
        a_src[i] = Abase + (size_t)(off + row0 + r) * KTOT + c8;
        a_dst[i] = smem_u32(&sh[AS_H(0) + r * LDB + c8]);
        b_src[i] = Bbase + (size_t)(e * NCOLS + n0 + r) * KTOT + c8;
        b_dst[i] = smem_u32(&sh[BS_H(0) + r * LDB + c8]);
    }
    const uint32_t FLIP = ASZ * 2;       // bytes between stages

    wmma::fragment<wmma::accumulator, 16, 16, 16, float> acc[2][4];
#pragma unroll
    for (int i = 0; i < 2; i++)
#pragma unroll
        for (int j = 0; j < 4; j++) wmma::fill_fragment(acc[i][j], 0.f);

    const int T = KTOT / BK;

    // prefetch stage 0
#pragma unroll
    for (int i = 0; i < 2; i++) { cp_async16(a_dst[i], a_src[i]); cp_async16(b_dst[i], b_src[i]); }
    cp_commit();

    for (int t = 0; t < T; t++) {
        const int b = t & 1;
        if (t + 1 < T) {
            const uint32_t f = (b ^ 1) ? FLIP : 0u;
#pragma unroll
            for (int i = 0; i < 2; i++) {
                cp_async16(a_dst[i] + f, a_src[i] + (size_t)(t + 1) * BK);
                cp_async16(b_dst[i] + f, b_src[i] + (size_t)(t + 1) * BK);
            }
            cp_commit();
            cp_wait<1>();
        } else {
            cp_wait<0>();
        }
        __syncthreads();

#pragma unroll
        for (int kk = 0; kk < BK; kk += 16) {
            wmma::fragment<wmma::matrix_a, 16, 16, 16, half, wmma::row_major> af[2];
            wmma::fragment<wmma::matrix_b, 16, 16, 16, half, wmma::col_major> bf[4];
            wmma::load_matrix_sync(af[0], &sh[AS_H(b) + (wm * 32 + 0)  * LDB + kk], LDB);
            wmma::load_matrix_sync(af[1], &sh[AS_H(b) + (wm * 32 + 16) * LDB + kk], LDB);
#pragma unroll
            for (int j = 0; j < 4; j++)
                wmma::load_matrix_sync(bf[j], &sh[BS_H(b) + (wn * 64 + j * 16) * LDB + kk], LDB);
#pragma unroll
            for (int i = 0; i < 2; i++)
#pragma unroll
                for (int j = 0; j < 4; j++)
                    wmma::mma_sync(acc[i][j], af[i], bf[j], acc[i][j]);
        }
        __syncthreads();
    }

    // epilogue: two N-half passes, fp32 staging overlaying the load buffers
    float* Cs = (float*)sh;
#pragma unroll
    for (int p = 0; p < 2; p++) {
        if (wn == p) {
#pragma unroll
            for (int i = 0; i < 2; i++)
#pragma unroll
                for (int j = 0; j < 4; j++)
                    wmma::store_matrix_sync(&Cs[(wm * 32 + i * 16) * LDC + j * 16],
                                            acc[i][j], LDC, wmma::mem_row_major);
        }
        __syncthreads();

#pragma unroll
        for (int i = 0; i < 8; i++) {
            int idx4 = tid + i * NTH;    // 0..2047 float4 = 128x64
            int r    = idx4 >> 4;
            int c4   = (idx4 & 15) * 4;
            if (row0 + r < cnt) {
                int slot = off + row0 + r;
                int col  = n0 + p * 64 + c4;
                float4 v = *(const float4*)&Cs[r * LDC + c4];
                const float4 bv = *(const float4*)&bias[e * NCOLS + col];
                if (MODE == 0) {
                    __half2 h0 = __floats2half2_rn(fmaxf(v.x + bv.x, 0.f),
                                                   fmaxf(v.y + bv.y, 0.f));
                    __half2 h1 = __floats2half2_rn(fmaxf(v.z + bv.z, 0.f),
                                                   fmaxf(v.w + bv.w, 0.f));
                    uint2 o;
                    o.x = *(uint32_t*)&h0;
                    o.y = *(uint32_t*)&h1;
                    *(uint2*)&g_H[(size_t)slot * HDIM + col] = o;
                } else {
                    int tok = g_expert_tok[slot];
                    float w = g_expert_w[slot];
                    float* o = &outp[(size_t)tok * DIM + col];
                    atomicAdd(o + 0, (v.x + bv.x) * w);
                    atomicAdd(o + 1, (v.y + bv.y) * w);
                    atomicAdd(o + 2, (v.z + bv.z) * w);
                    atomicAdd(o + 3, (v.w + bv.w) * w);
                }
            }
        }
        __syncthreads();
    }
}

// ---------------- lb_loss ---------------------------------------------------
__global__ void loss_kernel(float* __restrict__ loss_out) {
    if (threadIdx.x == 0) {
        float nt = (float)g_nt;
        float s = 0.f;
        for (int e = 0; e < NEXP; e++)
            s += ((float)g_top1[e] / nt) * (g_colsum[e] / nt);
        *loss_out = (float)NEXP * s;
    }
}

// ---------------- launch -----------------------------------------------------
extern "C" void kernel_launch(void* const* d_in, const int* in_sizes, int n_in,
                              void* d_out, int out_size) {
    const float*         x      = (const float*)d_in[0];
    const unsigned char* pm     = (const unsigned char*)d_in[1];
    const float*         gate_w = (const float*)d_in[2];
    const float*         fc1_w  = (const float*)d_in[3];
    const float*         fc1_b  = (const float*)d_in[4];
    const float*         fc2_w  = (const float*)d_in[5];
    const float*         fc2_b  = (const float*)d_in[6];
    (void)in_sizes; (void)n_in; (void)out_size;

    float* out      = (float*)d_out;
    float* gate_out = out + (size_t)N_TOK * DIM;
    float* loss_out = gate_out + (size_t)N_TOK * NEXP;

    cudaFuncSetAttribute(gemm_kernel<DIM, 0>,
                         cudaFuncAttributeMaxDynamicSharedMemorySize, SMEM_BYTES);
    cudaFuncSetAttribute(gemm_kernel<HDIM, 1>,
                         cudaFuncAttributeMaxDynamicSharedMemorySize, SMEM_BYTES);

    cudaMemsetAsync(out, 0, (size_t)N_TOK * DIM * sizeof(float));
    init_kernel<<<1, 32>>>();
    gate_kernel<<<N_TOK / 8, 256>>>(x, pm, gate_w, gate_out);
    offsets_kernel<<<1, 32>>>();
    scatter_kernel<<<N_TOK / 256, 256>>>();
    gather_kernel<<<NSLOT, 256>>>(x);
    conv_w_kernel<0><<<2048, 256>>>((const float4*)fc1_w, NEXP * HDIM * DIM / 4);
    conv_w_kernel<1><<<2048, 256>>>((const float4*)fc2_w, NEXP * DIM * HDIM / 4);
    gemm_kernel<DIM, 0><<<dim3(HDIM / TN, NSLOT / TM, NEXP), NTH, SMEM_BYTES>>>(fc1_b, nullptr);
    gemm_kernel<HDIM, 1><<<dim3(DIM / TN, NSLOT / TM, NEXP), NTH, SMEM_BYTES>>>(fc2_b, out);
    loss_kernel<<<1, 32>>>(loss_out);
}

// round 7
// speedup vs baseline: 3.5433x; 1.3942x over previous
#include <cuda_runtime.h>
#include <cuda_fp16.h>
#include <mma.h>
#include <cstdint>

using namespace nvcuda;

#define N_TOK 4096
#define DIM   1024
#define NEXP  8
#define HDIM  2048
#define NSLOT 8192
#define PAD   128

// gemm tiling: block 128x128, 4 warps (2x2), warp tile 64x64, BK=32, 3 stages
#define TM 128
#define TN 128
#define BK 32
#define NTH 128
#define LDB 40            // smem row stride in halves (80B)
#define LDC 68            // epilogue fp32 row stride

#define STAGE_H (TM * LDB + TN * LDB)     // halves per stage (10240)
#define SMEM_BYTES (3 * STAGE_H * 2)      // 61440 B; epilogue overlay 34816 B fits

// ---------------- scratch (device globals) ----------------------------------
__device__ __align__(256) __half g_Xg[(size_t)(NSLOT + PAD) * DIM];
__device__ __align__(256) __half g_H [(size_t)(NSLOT + PAD) * HDIM];
__device__ __align__(256) __half g_w1h[(size_t)NEXP * HDIM * DIM];
__device__ __align__(256) __half g_w2h[(size_t)NEXP * DIM * HDIM];
__device__ int   g_expert_tok[NSLOT];
__device__ float g_expert_w[NSLOT];
__device__ int   g_tok_e[N_TOK * 2];
__device__ float g_tok_w[N_TOK * 2];
__device__ int   g_counts[NEXP];
__device__ int   g_cursor[NEXP];
__device__ int   g_offsets[NEXP + 1];
__device__ float g_colsum[NEXP];
__device__ int   g_top1[NEXP];
__device__ int   g_nt;

// ---------------- helpers ---------------------------------------------------
__device__ __forceinline__ uint32_t smem_u32(const void* p) {
    return (uint32_t)__cvta_generic_to_shared(p);
}
__device__ __forceinline__ void cp_async16(uint32_t dst, const void* src) {
    asm volatile("cp.async.cg.shared.global [%0], [%1], 16;\n" :: "r"(dst), "l"(src));
}
__device__ __forceinline__ void cp_commit() {
    asm volatile("cp.async.commit_group;\n" ::: "memory");
}
template<int N> __device__ __forceinline__ void cp_wait() {
    asm volatile("cp.async.wait_group %0;\n" :: "n"(N) : "memory");
}

// ---------------- init / gate / offsets / scatter (proven) ------------------
__global__ void init_kernel() {
    int t = threadIdx.x;
    if (t < NEXP) { g_counts[t] = 0; g_cursor[t] = 0; g_colsum[t] = 0.f; g_top1[t] = 0; }
    if (t == 0) g_nt = 0;
}

__global__ void gate_kernel(const float* __restrict__ x,
                            const unsigned char* __restrict__ pm,
                            const float* __restrict__ gw,
                            float* __restrict__ gate_out) {
    int warp = (blockIdx.x * blockDim.x + threadIdx.x) >> 5;
    int lane = threadIdx.x & 31;
    if (warp >= N_TOK) return;
    const int n = warp;
    const float* xr = x + (size_t)n * DIM;

    float acc[NEXP];
#pragma unroll
    for (int e = 0; e < NEXP; e++) acc[e] = 0.f;
    for (int d = lane; d < DIM; d += 32) {
        float xv = xr[d];
#pragma unroll
        for (int e = 0; e < NEXP; e++) acc[e] += xv * gw[e * DIM + d];
    }
#pragma unroll
    for (int e = 0; e < NEXP; e++) {
#pragma unroll
        for (int o = 16; o > 0; o >>= 1)
            acc[e] += __shfl_xor_sync(0xffffffffu, acc[e], o);
    }
    if (lane == 0) {
        bool masked = (pm[n] != 0);
        float m = acc[0];
#pragma unroll
        for (int e = 1; e < NEXP; e++) m = fmaxf(m, acc[e]);
        float gv[NEXP]; float s = 0.f;
#pragma unroll
        for (int e = 0; e < NEXP; e++) { gv[e] = expf(acc[e] - m); s += gv[e]; }
        float inv = 1.f / s;
#pragma unroll
        for (int e = 0; e < NEXP; e++) {
            gv[e] *= inv;
            if (masked) gv[e] = 0.f;
            gate_out[(size_t)n * NEXP + e] = gv[e];
        }
        int e1 = 0;
#pragma unroll
        for (int e = 1; e < NEXP; e++) if (gv[e] > gv[e1]) e1 = e;
        int e2 = -1;
#pragma unroll
        for (int e = 0; e < NEXP; e++) {
            if (e == e1) continue;
            if (e2 < 0 || gv[e] > gv[e2]) e2 = e;
        }
        float den = gv[e1] + gv[e2];
        if (den == 0.f) den = 1.f;
        g_tok_e[2 * n + 0] = e1;
        g_tok_e[2 * n + 1] = e2;
        g_tok_w[2 * n + 0] = gv[e1] / den;
        g_tok_w[2 * n + 1] = gv[e2] / den;
        atomicAdd(&g_counts[e1], 1);
        atomicAdd(&g_counts[e2], 1);
        if (!masked) { atomicAdd(&g_top1[e1], 1); atomicAdd(&g_nt, 1); }
#pragma unroll
        for (int e = 0; e < NEXP; e++) atomicAdd(&g_colsum[e], gv[e]);
    }
}

__global__ void offsets_kernel() {
    if (threadIdx.x == 0) {
        int off = 0;
        for (int e = 0; e < NEXP; e++) { g_offsets[e] = off; off += g_counts[e]; }
        g_offsets[NEXP] = off;
    }
}

__global__ void scatter_kernel() {
    int n = blockIdx.x * blockDim.x + threadIdx.x;
    if (n >= N_TOK) return;
#pragma unroll
    for (int s = 0; s < 2; s++) {
        int e = g_tok_e[2 * n + s];
        int pos = g_offsets[e] + atomicAdd(&g_cursor[e], 1);
        g_expert_tok[pos] = n;
        g_expert_w[pos]   = g_tok_w[2 * n + s];
    }
}

// ---------------- gather (fp32 -> fp16 rows of X) ---------------------------
__global__ void gather_kernel(const float* __restrict__ x) {
    int s = blockIdx.x;
    int tok = g_expert_tok[s];
    const float4* src = (const float4*)(x + (size_t)tok * DIM);
    uint2* dst = (uint2*)(g_Xg + (size_t)s * DIM);
    int c = threadIdx.x;
    float4 v = src[c];
    __half2 h0 = __floats2half2_rn(v.x, v.y);
    __half2 h1 = __floats2half2_rn(v.z, v.w);
    uint2 o;
    o.x = *(uint32_t*)&h0;
    o.y = *(uint32_t*)&h1;
    dst[c] = o;
}

template<int WHICH>
__global__ void conv_w_kernel(const float4* __restrict__ src, int n4) {
    uint2* dst = (uint2*)(WHICH == 0 ? g_w1h : g_w2h);
    int stride = gridDim.x * blockDim.x;
    for (int i = blockIdx.x * blockDim.x + threadIdx.x; i < n4; i += stride) {
        float4 v = src[i];
        __half2 h0 = __floats2half2_rn(v.x, v.y);
        __half2 h1 = __floats2half2_rn(v.z, v.w);
        uint2 o;
        o.x = *(uint32_t*)&h0;
        o.y = *(uint32_t*)&h1;
        dst[i] = o;
    }
}

// ---------------- grouped GEMM (fp16 wmma, 64x64 warp tile, 3-stage) --------
// MODE 0: g_H = half(relu(Xg @ w1h^T + b1))    KTOT=DIM,  NCOLS=HDIM
// MODE 1: out[tok] += w * (g_H @ w2h^T + b2)   KTOT=HDIM, NCOLS=DIM
template<int KTOT, int MODE>
__global__ __launch_bounds__(NTH, 2) void gemm_kernel(const float* __restrict__ bias,
                                                      float* __restrict__ outp) {
    const int e = blockIdx.z;
    const int off = g_offsets[e];
    const int cnt = g_offsets[e + 1] - off;
    const int row0 = blockIdx.y * TM;
    if (row0 >= cnt) return;
    const int n0 = blockIdx.x * TN;
    const int NCOLS = (MODE == 0) ? HDIM : DIM;

    extern __shared__ __align__(16) __half sh[];

    const int tid  = threadIdx.x;
    const int warp = tid >> 5;
    const int wm   = warp >> 1;          // 0..1 : 64-row strip
    const int wn   = warp & 1;           // 0..1 : 64-col strip

    const __half* Abase = (MODE == 0) ? g_Xg : g_H;
    const __half* Bbase = (MODE == 0) ? g_w1h : g_w2h;

    // cp.async: per stage A = 512 chunks (16B), B = 512; 4 A + 4 B per thread
    const __half* a_src[4];
    uint32_t a_off[4];                   // byte offsets within stage
    const __half* b_src[4];
    uint32_t b_off[4];
#pragma unroll
    for (int i = 0; i < 4; i++) {
        int cid = tid + i * NTH;         // 0..511
        int r   = cid >> 2;              // 0..127
        int c8  = (cid & 3) * 8;         // 0,8,16,24 halves
        a_src[i] = Abase + (size_t)(off + row0 + r) * KTOT + c8;
        a_off[i] = (uint32_t)((r * LDB + c8) * 2);
        b_src[i] = Bbase + (size_t)(e * NCOLS + n0 + r) * KTOT + c8;
        b_off[i] = (uint32_t)((TM * LDB + r * LDB + c8) * 2);
    }
    const uint32_t sbase = smem_u32(sh);
    const uint32_t STAGE_B = STAGE_H * 2;

    wmma::fragment<wmma::accumulator, 16, 16, 16, float> acc[4][4];
#pragma unroll
    for (int i = 0; i < 4; i++)
#pragma unroll
        for (int j = 0; j < 4; j++) wmma::fill_fragment(acc[i][j], 0.f);

    const int T = KTOT / BK;

    // prefetch stages 0 and 1
#pragma unroll
    for (int s = 0; s < 2; s++) {
#pragma unroll
        for (int i = 0; i < 4; i++) {
            cp_async16(sbase + s * STAGE_B + a_off[i], a_src[i] + (size_t)s * BK);
            cp_async16(sbase + s * STAGE_B + b_off[i], b_src[i] + (size_t)s * BK);
        }
        cp_commit();
    }

    int buf = 0;
    for (int t = 0; t < T; t++) {
        if (t < T - 1) cp_wait<1>(); else cp_wait<0>();
        __syncthreads();

        if (t + 2 < T) {
            int pb = (buf + 2 >= 3) ? buf - 1 : buf + 2;
            uint32_t pbb = sbase + pb * STAGE_B;
#pragma unroll
            for (int i = 0; i < 4; i++) {
                cp_async16(pbb + a_off[i], a_src[i] + (size_t)(t + 2) * BK);
                cp_async16(pbb + b_off[i], b_src[i] + (size_t)(t + 2) * BK);
            }
            cp_commit();
        }

        const __half* As = sh + (size_t)buf * STAGE_H;
        const __half* Bs = As + TM * LDB;
#pragma unroll
        for (int kk = 0; kk < BK; kk += 16) {
            wmma::fragment<wmma::matrix_a, 16, 16, 16, half, wmma::row_major> af[4];
            wmma::fragment<wmma::matrix_b, 16, 16, 16, half, wmma::col_major> bf[4];
#pragma unroll
            for (int i = 0; i < 4; i++)
                wmma::load_matrix_sync(af[i], &As[(wm * 64 + i * 16) * LDB + kk], LDB);
#pragma unroll
            for (int j = 0; j < 4; j++)
                wmma::load_matrix_sync(bf[j], &Bs[(wn * 64 + j * 16) * LDB + kk], LDB);
#pragma unroll
            for (int i = 0; i < 4; i++)
#pragma unroll
                for (int j = 0; j < 4; j++)
                    wmma::mma_sync(acc[i][j], af[i], bf[j], acc[i][j]);
        }
        __syncthreads();
        buf = (buf + 1 >= 3) ? 0 : buf + 1;
    }

    // epilogue: two 64-col passes through fp32 staging (overlay on load smem)
    float* Cs = (float*)sh;
#pragma unroll
    for (int p = 0; p < 2; p++) {
        if (wn == p) {
#pragma unroll
            for (int i = 0; i < 4; i++)
#pragma unroll
                for (int j = 0; j < 4; j++)
                    wmma::store_matrix_sync(&Cs[(wm * 64 + i * 16) * LDC + j * 16],
                                            acc[i][j], LDC, wmma::mem_row_major);
        }
        __syncthreads();

#pragma unroll
        for (int i = 0; i < 16; i++) {
            int idx4 = tid + i * NTH;    // 0..2047 float4 = 128x64
            int r    = idx4 >> 4;
            int c4   = (idx4 & 15) * 4;
            if (row0 + r < cnt) {
                int slot = off + row0 + r;
                int col  = n0 + p * 64 + c4;
                float4 v = *(const float4*)&Cs[r * LDC + c4];
                const float4 bv = *(const float4*)&bias[e * NCOLS + col];
                if (MODE == 0) {
                    __half2 h0 = __floats2half2_rn(fmaxf(v.x + bv.x, 0.f),
                                                   fmaxf(v.y + bv.y, 0.f));
                    __half2 h1 = __floats2half2_rn(fmaxf(v.z + bv.z, 0.f),
                                                   fmaxf(v.w + bv.w, 0.f));
                    uint2 o;
                    o.x = *(uint32_t*)&h0;
                    o.y = *(uint32_t*)&h1;
                    *(uint2*)&g_H[(size_t)slot * HDIM + col] = o;
                } else {
                    int tok = g_expert_tok[slot];
                    float w = g_expert_w[slot];
                    float* o = &outp[(size_t)tok * DIM + col];
                    atomicAdd(o + 0, (v.x + bv.x) * w);
                    atomicAdd(o + 1, (v.y + bv.y) * w);
                    atomicAdd(o + 2, (v.z + bv.z) * w);
                    atomicAdd(o + 3, (v.w + bv.w) * w);
                }
            }
        }
        __syncthreads();
    }
}

// ---------------- lb_loss ---------------------------------------------------
__global__ void loss_kernel(float* __restrict__ loss_out) {
    if (threadIdx.x == 0) {
        float nt = (float)g_nt;
        float s = 0.f;
        for (int e = 0; e < NEXP; e++)
            s += ((float)g_top1[e] / nt) * (g_colsum[e] / nt);
        *loss_out = (float)NEXP * s;
    }
}

// ---------------- launch -----------------------------------------------------
extern "C" void kernel_launch(void* const* d_in, const int* in_sizes, int n_in,
                              void* d_out, int out_size) {
    const float*         x      = (const float*)d_in[0];
    const unsigned char* pm     = (const unsigned char*)d_in[1];
    const float*         gate_w = (const float*)d_in[2];
    const float*         fc1_w  = (const float*)d_in[3];
    const float*         fc1_b  = (const float*)d_in[4];
    const float*         fc2_w  = (const float*)d_in[5];
    const float*         fc2_b  = (const float*)d_in[6];
    (void)in_sizes; (void)n_in; (void)out_size;

    float* out      = (float*)d_out;
    float* gate_out = out + (size_t)N_TOK * DIM;
    float* loss_out = gate_out + (size_t)N_TOK * NEXP;

    cudaFuncSetAttribute(gemm_kernel<DIM, 0>,
                         cudaFuncAttributeMaxDynamicSharedMemorySize, SMEM_BYTES);
    cudaFuncSetAttribute(gemm_kernel<HDIM, 1>,
                         cudaFuncAttributeMaxDynamicSharedMemorySize, SMEM_BYTES);

    cudaMemsetAsync(out, 0, (size_t)N_TOK * DIM * sizeof(float));
    init_kernel<<<1, 32>>>();
    gate_kernel<<<N_TOK / 8, 256>>>(x, pm, gate_w, gate_out);
    offsets_kernel<<<1, 32>>>();
    scatter_kernel<<<N_TOK / 256, 256>>>();
    gather_kernel<<<NSLOT, 256>>>(x);
    conv_w_kernel<0><<<2048, 256>>>((const float4*)fc1_w, NEXP * HDIM * DIM / 4);
    conv_w_kernel<1><<<2048, 256>>>((const float4*)fc2_w, NEXP * DIM * HDIM / 4);
    gemm_kernel<DIM, 0><<<dim3(HDIM / TN, NSLOT / TM, NEXP), NTH, SMEM_BYTES>>>(fc1_b, nullptr);
    gemm_kernel<HDIM, 1><<<dim3(DIM / TN, NSLOT / TM, NEXP), NTH, SMEM_BYTES>>>(fc2_b, out);
    loss_kernel<<<1, 32>>>(loss_out);
}

// round 8
// speedup vs baseline: 3.5724x; 1.0082x over previous
#include <cuda_runtime.h>
#include <cuda_fp16.h>
#include <mma.h>
#include <cstdint>

using namespace nvcuda;

#define N_TOK 4096
#define DIM   1024
#define NEXP  8
#define HDIM  2048
#define NSLOT 8192
#define PAD   128

// gemm tiling: block 128x128, 4 warps (2x2), warp tile 64x64, BK=32, 3 stages
#define TM 128
#define TN 128
#define BK 32
#define NTH 128
#define LDB 40            // smem row stride in halves (80B)
#define LDC 68            // epilogue fp32 row stride

#define STAGE_H (TM * LDB + TN * LDB)     // halves per stage (10240)
#define SMEM_BYTES (3 * STAGE_H * 2)      // 61440 B; epilogue overlay 34816 B fits

// ---------------- scratch (device globals) ----------------------------------
__device__ __align__(256) __half g_xh[(size_t)N_TOK * DIM];           // x in fp16
__device__ __align__(256) __half g_H [(size_t)(NSLOT + PAD) * HDIM];  // relu out fp16
__device__ __align__(256) __half g_w1h[(size_t)NEXP * HDIM * DIM];
__device__ __align__(256) __half g_w2h[(size_t)NEXP * DIM * HDIM];
__device__ __align__(256) float  g_O [(size_t)NSLOT * DIM];           // per-slot fc2 out
__device__ int   g_expert_tok[NSLOT];
__device__ float g_expert_w[NSLOT];
__device__ int   g_tok_slot[N_TOK * 2];
__device__ int   g_tok_e[N_TOK * 2];
__device__ float g_tok_w[N_TOK * 2];
__device__ int   g_counts[NEXP];
__device__ int   g_cursor[NEXP];
__device__ int   g_offsets[NEXP + 1];
__device__ float g_colsum[NEXP];
__device__ int   g_top1[NEXP];
__device__ int   g_nt;

// ---------------- helpers ---------------------------------------------------
__device__ __forceinline__ uint32_t smem_u32(const void* p) {
    return (uint32_t)__cvta_generic_to_shared(p);
}
__device__ __forceinline__ void cp_async16(uint32_t dst, const void* src) {
    asm volatile("cp.async.cg.shared.global [%0], [%1], 16;\n" :: "r"(dst), "l"(src));
}
__device__ __forceinline__ void cp_commit() {
    asm volatile("cp.async.commit_group;\n" ::: "memory");
}
template<int N> __device__ __forceinline__ void cp_wait() {
    asm volatile("cp.async.wait_group %0;\n" :: "n"(N) : "memory");
}

// ---------------- init / gate / offsets / scatter (proven) ------------------
__global__ void init_kernel() {
    int t = threadIdx.x;
    if (t < NEXP) { g_counts[t] = 0; g_cursor[t] = 0; g_colsum[t] = 0.f; g_top1[t] = 0; }
    if (t == 0) g_nt = 0;
}

__global__ void gate_kernel(const float* __restrict__ x,
                            const unsigned char* __restrict__ pm,
                            const float* __restrict__ gw,
                            float* __restrict__ gate_out) {
    int warp = (blockIdx.x * blockDim.x + threadIdx.x) >> 5;
    int lane = threadIdx.x & 31;
    if (warp >= N_TOK) return;
    const int n = warp;
    const float* xr = x + (size_t)n * DIM;

    float acc[NEXP];
#pragma unroll
    for (int e = 0; e < NEXP; e++) acc[e] = 0.f;
    for (int d = lane; d < DIM; d += 32) {
        float xv = xr[d];
#pragma unroll
        for (int e = 0; e < NEXP; e++) acc[e] += xv * gw[e * DIM + d];
    }
#pragma unroll
    for (int e = 0; e < NEXP; e++) {
#pragma unroll
        for (int o = 16; o > 0; o >>= 1)
            acc[e] += __shfl_xor_sync(0xffffffffu, acc[e], o);
    }
    if (lane == 0) {
        bool masked = (pm[n] != 0);
        float m = acc[0];
#pragma unroll
        for (int e = 1; e < NEXP; e++) m = fmaxf(m, acc[e]);
        float gv[NEXP]; float s = 0.f;
#pragma unroll
        for (int e = 0; e < NEXP; e++) { gv[e] = expf(acc[e] - m); s += gv[e]; }
        float inv = 1.f / s;
#pragma unroll
        for (int e = 0; e < NEXP; e++) {
            gv[e] *= inv;
            if (masked) gv[e] = 0.f;
            gate_out[(size_t)n * NEXP + e] = gv[e];
        }
        int e1 = 0;
#pragma unroll
        for (int e = 1; e < NEXP; e++) if (gv[e] > gv[e1]) e1 = e;
        int e2 = -1;
#pragma unroll
        for (int e = 0; e < NEXP; e++) {
            if (e == e1) continue;
            if (e2 < 0 || gv[e] > gv[e2]) e2 = e;
        }
        float den = gv[e1] + gv[e2];
        if (den == 0.f) den = 1.f;
        g_tok_e[2 * n + 0] = e1;
        g_tok_e[2 * n + 1] = e2;
        g_tok_w[2 * n + 0] = gv[e1] / den;
        g_tok_w[2 * n + 1] = gv[e2] / den;
        atomicAdd(&g_counts[e1], 1);
        atomicAdd(&g_counts[e2], 1);
        if (!masked) { atomicAdd(&g_top1[e1], 1); atomicAdd(&g_nt, 1); }
#pragma unroll
        for (int e = 0; e < NEXP; e++) atomicAdd(&g_colsum[e], gv[e]);
    }
}

__global__ void offsets_kernel() {
    if (threadIdx.x == 0) {
        int off = 0;
        for (int e = 0; e < NEXP; e++) { g_offsets[e] = off; off += g_counts[e]; }
        g_offsets[NEXP] = off;
    }
}

__global__ void scatter_kernel() {
    int n = blockIdx.x * blockDim.x + threadIdx.x;
    if (n >= N_TOK) return;
#pragma unroll
    for (int s = 0; s < 2; s++) {
        int e = g_tok_e[2 * n + s];
        int pos = g_offsets[e] + atomicAdd(&g_cursor[e], 1);
        g_expert_tok[pos] = n;
        g_expert_w[pos]   = g_tok_w[2 * n + s];
        g_tok_slot[2 * n + s] = pos;
    }
}

// ---------------- fp32 -> fp16 conversion passes -----------------------------
__global__ void conv_x_kernel(const float4* __restrict__ src) {
    // N_TOK*DIM floats = 1M float4
    int i = blockIdx.x * blockDim.x + threadIdx.x;
    float4 v = src[i];
    __half2 h0 = __floats2half2_rn(v.x, v.y);
    __half2 h1 = __floats2half2_rn(v.z, v.w);
    uint2 o;
    o.x = *(uint32_t*)&h0;
    o.y = *(uint32_t*)&h1;
    ((uint2*)g_xh)[i] = o;
}

template<int WHICH>
__global__ void conv_w_kernel(const float4* __restrict__ src, int n8) {
    uint4* dst = (uint4*)(WHICH == 0 ? g_w1h : g_w2h);
    int stride = gridDim.x * blockDim.x;
    for (int i = blockIdx.x * blockDim.x + threadIdx.x; i < n8; i += stride) {
        float4 v0 = src[2 * i];
        float4 v1 = src[2 * i + 1];
        __half2 h0 = __floats2half2_rn(v0.x, v0.y);
        __half2 h1 = __floats2half2_rn(v0.z, v0.w);
        __half2 h2 = __floats2half2_rn(v1.x, v1.y);
        __half2 h3 = __floats2half2_rn(v1.z, v1.w);
        uint4 o;
        o.x = *(uint32_t*)&h0;
        o.y = *(uint32_t*)&h1;
        o.z = *(uint32_t*)&h2;
        o.w = *(uint32_t*)&h3;
        dst[i] = o;
    }
}

// ---------------- grouped GEMM (fp16 wmma, 64x64 warp tile, 3-stage) --------
// MODE 0: g_H = half(relu(Xg @ w1h^T + b1))    KTOT=DIM,  NCOLS=HDIM  (A = gathered g_xh)
// MODE 1: g_O[slot] = w * (g_H @ w2h^T + b2)   KTOT=HDIM, NCOLS=DIM   (A = g_H)
template<int KTOT, int MODE>
__global__ __launch_bounds__(NTH, 2) void gemm_kernel(const float* __restrict__ bias) {
    const int e = blockIdx.z;
    const int off = g_offsets[e];
    const int cnt = g_offsets[e + 1] - off;
    const int row0 = blockIdx.y * TM;
    if (row0 >= cnt) return;
    const int n0 = blockIdx.x * TN;
    const int NCOLS = (MODE == 0) ? HDIM : DIM;

    extern __shared__ __align__(16) __half sh[];

    const int tid  = threadIdx.x;
    const int warp = tid >> 5;
    const int wm   = warp >> 1;          // 0..1 : 64-row strip
    const int wn   = warp & 1;           // 0..1 : 64-col strip

    const __half* Bbase = (MODE == 0) ? g_w1h : g_w2h;

    // cp.async: per stage A = 512 chunks (16B), B = 512; 4 A + 4 B per thread
    const __half* a_src[4];
    uint32_t a_off[4];                   // byte offsets within stage
    const __half* b_src[4];
    uint32_t b_off[4];
#pragma unroll
    for (int i = 0; i < 4; i++) {
        int cid = tid + i * NTH;         // 0..511
        int r   = cid >> 2;              // 0..127
        int c8  = (cid & 3) * 8;         // 0,8,16,24 halves
        int slot = off + row0 + r;
        if (slot > NSLOT - 1) slot = NSLOT - 1;
        if (MODE == 0) {
            int tok = g_expert_tok[slot];
            a_src[i] = g_xh + (size_t)tok * DIM + c8;
        } else {
            a_src[i] = g_H + (size_t)slot * HDIM + c8;
        }
        a_off[i] = (uint32_t)((r * LDB + c8) * 2);
        b_src[i] = Bbase + (size_t)(e * NCOLS + n0 + r) * KTOT + c8;
        b_off[i] = (uint32_t)((TM * LDB + r * LDB + c8) * 2);
    }
    const uint32_t sbase = smem_u32(sh);
    const uint32_t STAGE_B = STAGE_H * 2;

    wmma::fragment<wmma::accumulator, 16, 16, 16, float> acc[4][4];
#pragma unroll
    for (int i = 0; i < 4; i++)
#pragma unroll
        for (int j = 0; j < 4; j++) wmma::fill_fragment(acc[i][j], 0.f);

    const int T = KTOT / BK;

    // prefetch stages 0 and 1
#pragma unroll
    for (int s = 0; s < 2; s++) {
#pragma unroll
        for (int i = 0; i < 4; i++) {
            cp_async16(sbase + s * STAGE_B + a_off[i], a_src[i] + (size_t)s * BK);
            cp_async16(sbase + s * STAGE_B + b_off[i], b_src[i] + (size_t)s * BK);
        }
        cp_commit();
    }

    int buf = 0;
    for (int t = 0; t < T; t++) {
        if (t < T - 1) cp_wait<1>(); else cp_wait<0>();
        __syncthreads();     // orders: stage-t data visible AND all reads of the
                             // buffer we are about to overwrite (iter t-1) done

        if (t + 2 < T) {
            int pb = (buf + 2 >= 3) ? buf - 1 : buf + 2;
            uint32_t pbb = sbase + pb * STAGE_B;
#pragma unroll
            for (int i = 0; i < 4; i++) {
                cp_async16(pbb + a_off[i], a_src[i] + (size_t)(t + 2) * BK);
                cp_async16(pbb + b_off[i], b_src[i] + (size_t)(t + 2) * BK);
            }
            cp_commit();
        }

        const __half* As = sh + (size_t)buf * STAGE_H;
        const __half* Bs = As + TM * LDB;
#pragma unroll
        for (int kk = 0; kk < BK; kk += 16) {
            wmma::fragment<wmma::matrix_a, 16, 16, 16, half, wmma::row_major> af[4];
            wmma::fragment<wmma::matrix_b, 16, 16, 16, half, wmma::col_major> bf[4];
#pragma unroll
            for (int i = 0; i < 4; i++)
                wmma::load_matrix_sync(af[i], &As[(wm * 64 + i * 16) * LDB + kk], LDB);
#pragma unroll
            for (int j = 0; j < 4; j++)
                wmma::load_matrix_sync(bf[j], &Bs[(wn * 64 + j * 16) * LDB + kk], LDB);
#pragma unroll
            for (int i = 0; i < 4; i++)
#pragma unroll
                for (int j = 0; j < 4; j++)
                    wmma::mma_sync(acc[i][j], af[i], bf[j], acc[i][j]);
        }
        // no trailing sync: next iter's leading sync provides the WAR ordering
        buf = (buf + 1 >= 3) ? 0 : buf + 1;
    }
    __syncthreads();         // protect smem overlay before epilogue staging

    // epilogue: two 64-col passes through fp32 staging (overlay on load smem)
    float* Cs = (float*)sh;
#pragma unroll
    for (int p = 0; p < 2; p++) {
        if (wn == p) {
#pragma unroll
            for (int i = 0; i < 4; i++)
#pragma unroll
                for (int j = 0; j < 4; j++)
                    wmma::store_matrix_sync(&Cs[(wm * 64 + i * 16) * LDC + j * 16],
                                            acc[i][j], LDC, wmma::mem_row_major);
        }
        __syncthreads();

#pragma unroll
        for (int i = 0; i < 16; i++) {
            int idx4 = tid + i * NTH;    // 0..2047 float4 = 128x64
            int r    = idx4 >> 4;
            int c4   = (idx4 & 15) * 4;
            if (row0 + r < cnt) {
                int slot = off + row0 + r;
                int col  = n0 + p * 64 + c4;
                float4 v = *(const float4*)&Cs[r * LDC + c4];
                const float4 bv = *(const float4*)&bias[e * NCOLS + col];
                if (MODE == 0) {
                    __half2 h0 = __floats2half2_rn(fmaxf(v.x + bv.x, 0.f),
                                                   fmaxf(v.y + bv.y, 0.f));
                    __half2 h1 = __floats2half2_rn(fmaxf(v.z + bv.z, 0.f),
                                                   fmaxf(v.w + bv.w, 0.f));
                    uint2 o;
                    o.x = *(uint32_t*)&h0;
                    o.y = *(uint32_t*)&h1;
                    *(uint2*)&g_H[(size_t)slot * HDIM + col] = o;
                } else {
                    float w = g_expert_w[slot];
                    float4 o;
                    o.x = (v.x + bv.x) * w;
                    o.y = (v.y + bv.y) * w;
                    o.z = (v.z + bv.z) * w;
                    o.w = (v.w + bv.w) * w;
                    *(float4*)&g_O[(size_t)slot * DIM + col] = o;
                }
            }
        }
        __syncthreads();
    }
}

// ---------------- combine: out[tok] = O[slot0] + O[slot1] -------------------
__global__ void combine_kernel(float* __restrict__ out) {
    int n  = blockIdx.x;                  // token
    int c4 = threadIdx.x;                 // 0..255 float4 per row
    int s0 = g_tok_slot[2 * n + 0];
    int s1 = g_tok_slot[2 * n + 1];
    float4 a = ((const float4*)(g_O + (size_t)s0 * DIM))[c4];
    float4 b = ((const float4*)(g_O + (size_t)s1 * DIM))[c4];
    float4 o;
    o.x = a.x + b.x; o.y = a.y + b.y; o.z = a.z + b.z; o.w = a.w + b.w;
    ((float4*)(out + (size_t)n * DIM))[c4] = o;
}

// ---------------- lb_loss ---------------------------------------------------
__global__ void loss_kernel(float* __restrict__ loss_out) {
    if (threadIdx.x == 0) {
        float nt = (float)g_nt;
        float s = 0.f;
        for (int e = 0; e < NEXP; e++)
            s += ((float)g_top1[e] / nt) * (g_colsum[e] / nt);
        *loss_out = (float)NEXP * s;
    }
}

// ---------------- launch -----------------------------------------------------
extern "C" void kernel_launch(void* const* d_in, const int* in_sizes, int n_in,
                              void* d_out, int out_size) {
    const float*         x      = (const float*)d_in[0];
    const unsigned char* pm     = (const unsigned char*)d_in[1];
    const float*         gate_w = (const float*)d_in[2];
    const float*         fc1_w  = (const float*)d_in[3];
    const float*         fc1_b  = (const float*)d_in[4];
    const float*         fc2_w  = (const float*)d_in[5];
    const float*         fc2_b  = (const float*)d_in[6];
    (void)in_sizes; (void)n_in; (void)out_size;

    float* out      = (float*)d_out;
    float* gate_out = out + (size_t)N_TOK * DIM;
    float* loss_out = gate_out + (size_t)N_TOK * NEXP;

    cudaFuncSetAttribute(gemm_kernel<DIM, 0>,
                         cudaFuncAttributeMaxDynamicSharedMemorySize, SMEM_BYTES);
    cudaFuncSetAttribute(gemm_kernel<HDIM, 1>,
                         cudaFuncAttributeMaxDynamicSharedMemorySize, SMEM_BYTES);

    init_kernel<<<1, 32>>>();
    gate_kernel<<<N_TOK / 8, 256>>>(x, pm, gate_w, gate_out);
    offsets_kernel<<<1, 32>>>();
    scatter_kernel<<<N_TOK / 256, 256>>>();
    conv_x_kernel<<<N_TOK * DIM / 4 / 256, 256>>>((const float4*)x);
    conv_w_kernel<0><<<2048, 256>>>((const float4*)fc1_w, NEXP * HDIM * DIM / 8);
    conv_w_kernel<1><<<2048, 256>>>((const float4*)fc2_w, NEXP * DIM * HDIM / 8);
    gemm_kernel<DIM, 0><<<dim3(HDIM / TN, NSLOT / TM, NEXP), NTH, SMEM_BYTES>>>(fc1_b);
    gemm_kernel<HDIM, 1><<<dim3(DIM / TN, NSLOT / TM, NEXP), NTH, SMEM_BYTES>>>(fc2_b);
    combine_kernel<<<N_TOK, DIM / 4>>>(out);
    loss_kernel<<<1, 32>>>(loss_out);
}

// round 9
// speedup vs baseline: 3.7113x; 1.0389x over previous
#include <cuda_runtime.h>
#include <cuda_fp16.h>
#include <mma.h>
#include <cstdint>

using namespace nvcuda;

#define N_TOK 4096
#define DIM   1024
#define NEXP  8
#define HDIM  2048
#define NSLOT 8192
#define PAD   128

// gemm tiling: block 128x128, 4 warps (2x2), warp tile 64x64, BK=32, 3 stages
#define TM 128
#define TN 128
#define BK 32
#define NTH 128
#define LDB 40            // smem row stride in halves (80B)
#define LDC 68            // epilogue fp32 row stride

#define STAGE_H (TM * LDB + TN * LDB)     // halves per stage (10240)
#define SMEM_BYTES (3 * STAGE_H * 2)      // 61440 B; epilogue overlay 34816 B fits

// ---------------- scratch (device globals) ----------------------------------
__device__ __align__(256) __half g_xh[(size_t)N_TOK * DIM];           // x in fp16
__device__ __align__(256) __half g_H [(size_t)(NSLOT + PAD) * HDIM];  // relu out fp16
__device__ __align__(256) __half g_w1h[(size_t)NEXP * HDIM * DIM];
__device__ __align__(256) __half g_w2h[(size_t)NEXP * DIM * HDIM];
__device__ __align__(256) float  g_O [(size_t)NSLOT * DIM];           // per-slot fc2 out
__device__ int   g_expert_tok[NSLOT];
__device__ float g_expert_w[NSLOT];
__device__ int   g_tok_slot[N_TOK * 2];
__device__ int   g_tok_e[N_TOK * 2];
__device__ float g_tok_w[N_TOK * 2];
__device__ int   g_counts[NEXP];
__device__ int   g_cursor[NEXP];
__device__ int   g_offsets[NEXP + 1];
__device__ float g_colsum[NEXP];
__device__ int   g_top1[NEXP];
__device__ int   g_nt;

// ---------------- helpers ---------------------------------------------------
__device__ __forceinline__ uint32_t smem_u32(const void* p) {
    return (uint32_t)__cvta_generic_to_shared(p);
}
__device__ __forceinline__ void cp_async16(uint32_t dst, const void* src) {
    asm volatile("cp.async.cg.shared.global [%0], [%1], 16;\n" :: "r"(dst), "l"(src));
}
__device__ __forceinline__ void cp_commit() {
    asm volatile("cp.async.commit_group;\n" ::: "memory");
}
template<int N> __device__ __forceinline__ void cp_wait() {
    asm volatile("cp.async.wait_group %0;\n" :: "n"(N) : "memory");
}

// ---------------- init -------------------------------------------------------
__global__ void init_kernel() {
    int t = threadIdx.x;
    if (t < NEXP) { g_counts[t] = 0; g_cursor[t] = 0; g_colsum[t] = 0.f; g_top1[t] = 0; }
    if (t == 0) g_nt = 0;
}

// ---------------- gate (fused with x -> fp16 conversion) --------------------
// 256 threads = 8 warps = 8 tokens per block; gate_w staged in smem.
__global__ __launch_bounds__(256) void gate_kernel(
        const float* __restrict__ x,
        const unsigned char* __restrict__ pm,
        const float* __restrict__ gw,
        float* __restrict__ gate_out) {
    __shared__ float gw_s[NEXP * DIM];   // 32 KB

    const int tid = threadIdx.x;
    for (int i = tid; i < NEXP * DIM / 4; i += 256)
        ((float4*)gw_s)[i] = ((const float4*)gw)[i];
    __syncthreads();

    const int wid  = tid >> 5;
    const int lane = tid & 31;
    const int n = blockIdx.x * 8 + wid;
    const float* xr = x + (size_t)n * DIM;

    float acc[NEXP];
#pragma unroll
    for (int e = 0; e < NEXP; e++) acc[e] = 0.f;

#pragma unroll
    for (int i = 0; i < DIM / 128; i++) {          // 8 iters, float4 per lane
        int d = i * 128 + lane * 4;
        float4 v = *(const float4*)&xr[d];
        // fused fp16 conversion of x
        __half2 h0 = __floats2half2_rn(v.x, v.y);
        __half2 h1 = __floats2half2_rn(v.z, v.w);
        uint2 o;
        o.x = *(uint32_t*)&h0;
        o.y = *(uint32_t*)&h1;
        *(uint2*)&g_xh[(size_t)n * DIM + d] = o;
#pragma unroll
        for (int e = 0; e < NEXP; e++) {
            const float4 w4 = *(const float4*)&gw_s[e * DIM + d];
            acc[e] += v.x * w4.x + v.y * w4.y + v.z * w4.z + v.w * w4.w;
        }
    }
#pragma unroll
    for (int e = 0; e < NEXP; e++) {
#pragma unroll
        for (int o = 16; o > 0; o >>= 1)
            acc[e] += __shfl_xor_sync(0xffffffffu, acc[e], o);
    }

    if (lane == 0) {
        bool masked = (pm[n] != 0);
        float m = acc[0];
#pragma unroll
        for (int e = 1; e < NEXP; e++) m = fmaxf(m, acc[e]);
        float gv[NEXP]; float s = 0.f;
#pragma unroll
        for (int e = 0; e < NEXP; e++) { gv[e] = expf(acc[e] - m); s += gv[e]; }
        float inv = 1.f / s;
#pragma unroll
        for (int e = 0; e < NEXP; e++) {
            gv[e] *= inv;
            if (masked) gv[e] = 0.f;
            gate_out[(size_t)n * NEXP + e] = gv[e];
        }
        int e1 = 0;
#pragma unroll
        for (int e = 1; e < NEXP; e++) if (gv[e] > gv[e1]) e1 = e;
        int e2 = -1;
#pragma unroll
        for (int e = 0; e < NEXP; e++) {
            if (e == e1) continue;
            if (e2 < 0 || gv[e] > gv[e2]) e2 = e;
        }
        float den = gv[e1] + gv[e2];
        if (den == 0.f) den = 1.f;
        g_tok_e[2 * n + 0] = e1;
        g_tok_e[2 * n + 1] = e2;
        g_tok_w[2 * n + 0] = gv[e1] / den;
        g_tok_w[2 * n + 1] = gv[e2] / den;
        atomicAdd(&g_counts[e1], 1);
        atomicAdd(&g_counts[e2], 1);
        if (!masked) { atomicAdd(&g_top1[e1], 1); atomicAdd(&g_nt, 1); }
#pragma unroll
        for (int e = 0; e < NEXP; e++) atomicAdd(&g_colsum[e], gv[e]);
    }
}

__global__ void offsets_kernel() {
    if (threadIdx.x == 0) {
        int off = 0;
        for (int e = 0; e < NEXP; e++) { g_offsets[e] = off; off += g_counts[e]; }
        g_offsets[NEXP] = off;
    }
}

__global__ void scatter_kernel() {
    int n = blockIdx.x * blockDim.x + threadIdx.x;
    if (n >= N_TOK) return;
#pragma unroll
    for (int s = 0; s < 2; s++) {
        int e = g_tok_e[2 * n + s];
        int pos = g_offsets[e] + atomicAdd(&g_cursor[e], 1);
        g_expert_tok[pos] = n;
        g_expert_w[pos]   = g_tok_w[2 * n + s];
        g_tok_slot[2 * n + s] = pos;
    }
}

// ---------------- weight fp32 -> fp16 conversion ----------------------------
template<int WHICH>
__global__ void conv_w_kernel(const float4* __restrict__ src, int n8) {
    uint4* dst = (uint4*)(WHICH == 0 ? g_w1h : g_w2h);
    int stride = gridDim.x * blockDim.x;
    for (int i = blockIdx.x * blockDim.x + threadIdx.x; i < n8; i += stride) {
        float4 v0 = src[2 * i];
        float4 v1 = src[2 * i + 1];
        __half2 h0 = __floats2half2_rn(v0.x, v0.y);
        __half2 h1 = __floats2half2_rn(v0.z, v0.w);
        __half2 h2 = __floats2half2_rn(v1.x, v1.y);
        __half2 h3 = __floats2half2_rn(v1.z, v1.w);
        uint4 o;
        o.x = *(uint32_t*)&h0;
        o.y = *(uint32_t*)&h1;
        o.z = *(uint32_t*)&h2;
        o.w = *(uint32_t*)&h3;
        dst[i] = o;
    }
}

// ---------------- grouped GEMM (fp16 wmma, 64x64 warp tile, 3-stage) --------
// MODE 0: g_H = half(relu(Xg @ w1h^T + b1))    KTOT=DIM,  NCOLS=HDIM  (A = gathered g_xh)
// MODE 1: g_O[slot] = w * (g_H @ w2h^T + b2)   KTOT=HDIM, NCOLS=DIM   (A = g_H)
template<int KTOT, int MODE>
__global__ __launch_bounds__(NTH, 2) void gemm_kernel(const float* __restrict__ bias) {
    const int e = blockIdx.z;
    const int off = g_offsets[e];
    const int cnt = g_offsets[e + 1] - off;
    const int row0 = blockIdx.y * TM;
    if (row0 >= cnt) return;
    const int n0 = blockIdx.x * TN;
    const int NCOLS = (MODE == 0) ? HDIM : DIM;

    extern __shared__ __align__(16) __half sh[];

    const int tid  = threadIdx.x;
    const int warp = tid >> 5;
    const int wm   = warp >> 1;          // 0..1 : 64-row strip
    const int wn   = warp & 1;           // 0..1 : 64-col strip

    const __half* Bbase = (MODE == 0) ? g_w1h : g_w2h;

    // cp.async: per stage A = 512 chunks (16B), B = 512; 4 A + 4 B per thread
    const __half* a_src[4];
    uint32_t a_off[4];                   // byte offsets within stage
    const __half* b_src[4];
    uint32_t b_off[4];
#pragma unroll
    for (int i = 0; i < 4; i++) {
        int cid = tid + i * NTH;         // 0..511
        int r   = cid >> 2;              // 0..127
        int c8  = (cid & 3) * 8;         // 0,8,16,24 halves
        int slot = off + row0 + r;
        if (slot > NSLOT - 1) slot = NSLOT - 1;
        if (MODE == 0) {
            int tok = g_expert_tok[slot];
            a_src[i] = g_xh + (size_t)tok * DIM + c8;
        } else {
            a_src[i] = g_H + (size_t)slot * HDIM + c8;
        }
        a_off[i] = (uint32_t)((r * LDB + c8) * 2);
        b_src[i] = Bbase + (size_t)(e * NCOLS + n0 + r) * KTOT + c8;
        b_off[i] = (uint32_t)((TM * LDB + r * LDB + c8) * 2);
    }
    const uint32_t sbase = smem_u32(sh);
    const uint32_t STAGE_B = STAGE_H * 2;

    wmma::fragment<wmma::accumulator, 16, 16, 16, float> acc[4][4];
#pragma unroll
    for (int i = 0; i < 4; i++)
#pragma unroll
        for (int j = 0; j < 4; j++) wmma::fill_fragment(acc[i][j], 0.f);

    const int T = KTOT / BK;

    // prefetch stages 0 and 1
#pragma unroll
    for (int s = 0; s < 2; s++) {
#pragma unroll
        for (int i = 0; i < 4; i++) {
            cp_async16(sbase + s * STAGE_B + a_off[i], a_src[i] + (size_t)s * BK);
            cp_async16(sbase + s * STAGE_B + b_off[i], b_src[i] + (size_t)s * BK);
        }
        cp_commit();
    }

    int buf = 0;
    for (int t = 0; t < T; t++) {
        if (t < T - 1) cp_wait<1>(); else cp_wait<0>();
        __syncthreads();     // stage-t data visible AND prior reads of the
                             // buffer about to be overwritten are done

        if (t + 2 < T) {
            int pb = (buf + 2 >= 3) ? buf - 1 : buf + 2;
            uint32_t pbb = sbase + pb * STAGE_B;
#pragma unroll
            for (int i = 0; i < 4; i++) {
                cp_async16(pbb + a_off[i], a_src[i] + (size_t)(t + 2) * BK);
                cp_async16(pbb + b_off[i], b_src[i] + (size_t)(t + 2) * BK);
            }
            cp_commit();
        }

        const __half* As = sh + (size_t)buf * STAGE_H;
        const __half* Bs = As + TM * LDB;
#pragma unroll
        for (int kk = 0; kk < BK; kk += 16) {
            wmma::fragment<wmma::matrix_a, 16, 16, 16, half, wmma::row_major> af[4];
            wmma::fragment<wmma::matrix_b, 16, 16, 16, half, wmma::col_major> bf[4];
#pragma unroll
            for (int i = 0; i < 4; i++)
                wmma::load_matrix_sync(af[i], &As[(wm * 64 + i * 16) * LDB + kk], LDB);
#pragma unroll
            for (int j = 0; j < 4; j++)
                wmma::load_matrix_sync(bf[j], &Bs[(wn * 64 + j * 16) * LDB + kk], LDB);
#pragma unroll
            for (int i = 0; i < 4; i++)
#pragma unroll
                for (int j = 0; j < 4; j++)
                    wmma::mma_sync(acc[i][j], af[i], bf[j], acc[i][j]);
        }
        buf = (buf + 1 >= 3) ? 0 : buf + 1;
    }
    __syncthreads();         // protect smem overlay before epilogue staging

    // epilogue: two 64-col passes through fp32 staging (overlay on load smem)
    float* Cs = (float*)sh;
#pragma unroll
    for (int p = 0; p < 2; p++) {
        if (wn == p) {
#pragma unroll
            for (int i = 0; i < 4; i++)
#pragma unroll
                for (int j = 0; j < 4; j++)
                    wmma::store_matrix_sync(&Cs[(wm * 64 + i * 16) * LDC + j * 16],
                                            acc[i][j], LDC, wmma::mem_row_major);
        }
        __syncthreads();

#pragma unroll
        for (int i = 0; i < 16; i++) {
            int idx4 = tid + i * NTH;    // 0..2047 float4 = 128x64
            int r    = idx4 >> 4;
            int c4   = (idx4 & 15) * 4;
            if (row0 + r < cnt) {
                int slot = off + row0 + r;
                int col  = n0 + p * 64 + c4;
                float4 v = *(const float4*)&Cs[r * LDC + c4];
                const float4 bv = *(const float4*)&bias[e * NCOLS + col];
                if (MODE == 0) {
                    __half2 h0 = __floats2half2_rn(fmaxf(v.x + bv.x, 0.f),
                                                   fmaxf(v.y + bv.y, 0.f));
                    __half2 h1 = __floats2half2_rn(fmaxf(v.z + bv.z, 0.f),
                                                   fmaxf(v.w + bv.w, 0.f));
                    uint2 o;
                    o.x = *(uint32_t*)&h0;
                    o.y = *(uint32_t*)&h1;
                    *(uint2*)&g_H[(size_t)slot * HDIM + col] = o;
                } else {
                    float w = g_expert_w[slot];
                    float4 o;
                    o.x = (v.x + bv.x) * w;
                    o.y = (v.y + bv.y) * w;
                    o.z = (v.z + bv.z) * w;
                    o.w = (v.w + bv.w) * w;
                    *(float4*)&g_O[(size_t)slot * DIM + col] = o;
                }
            }
        }
        __syncthreads();
    }
}

// ---------------- combine (+ lb_loss on block 0) -----------------------------
__global__ void combine_kernel(float* __restrict__ out, float* __restrict__ loss_out) {
    int n  = blockIdx.x;                  // token
    int c4 = threadIdx.x;                 // 0..255 float4 per row
    if (n == 0 && c4 == 0) {
        float nt = (float)g_nt;
        float s = 0.f;
        for (int e = 0; e < NEXP; e++)
            s += ((float)g_top1[e] / nt) * (g_colsum[e] / nt);
        *loss_out = (float)NEXP * s;
    }
    int s0 = g_tok_slot[2 * n + 0];
    int s1 = g_tok_slot[2 * n + 1];
    float4 a = ((const float4*)(g_O + (size_t)s0 * DIM))[c4];
    float4 b = ((const float4*)(g_O + (size_t)s1 * DIM))[c4];
    float4 o;
    o.x = a.x + b.x; o.y = a.y + b.y; o.z = a.z + b.z; o.w = a.w + b.w;
    ((float4*)(out + (size_t)n * DIM))[c4] = o;
}

// ---------------- launch -----------------------------------------------------
extern "C" void kernel_launch(void* const* d_in, const int* in_sizes, int n_in,
                              void* d_out, int out_size) {
    const float*         x      = (const float*)d_in[0];
    const unsigned char* pm     = (const unsigned char*)d_in[1];
    const float*         gate_w = (const float*)d_in[2];
    const float*         fc1_w  = (const float*)d_in[3];
    const float*         fc1_b  = (const float*)d_in[4];
    const float*         fc2_w  = (const float*)d_in[5];
    const float*         fc2_b  = (const float*)d_in[6];
    (void)in_sizes; (void)n_in; (void)out_size;

    float* out      = (float*)d_out;
    float* gate_out = out + (size_t)N_TOK * DIM;
    float* loss_out = gate_out + (size_t)N_TOK * NEXP;

    cudaFuncSetAttribute(gemm_kernel<DIM, 0>,
                         cudaFuncAttributeMaxDynamicSharedMemorySize, SMEM_BYTES);
    cudaFuncSetAttribute(gemm_kernel<HDIM, 1>,
                         cudaFuncAttributeMaxDynamicSharedMemorySize, SMEM_BYTES);

    init_kernel<<<1, 32>>>();
    gate_kernel<<<N_TOK / 8, 256>>>(x, pm, gate_w, gate_out);
    offsets_kernel<<<1, 32>>>();
    scatter_kernel<<<N_TOK / 256, 256>>>();
    conv_w_kernel<0><<<2048, 256>>>((const float4*)fc1_w, NEXP * HDIM * DIM / 8);
    conv_w_kernel<1><<<2048, 256>>>((const float4*)fc2_w, NEXP * DIM * HDIM / 8);
    gemm_kernel<DIM, 0><<<dim3(HDIM / TN, NSLOT / TM, NEXP), NTH, SMEM_BYTES>>>(fc1_b);
    gemm_kernel<HDIM, 1><<<dim3(DIM / TN, NSLOT / TM, NEXP), NTH, SMEM_BYTES>>>(fc2_b);
    combine_kernel<<<N_TOK, DIM / 4>>>(out, loss_out);
}

// round 10
// speedup vs baseline: 3.9012x; 1.0512x over previous
#include <cuda_runtime.h>
#include <cuda_fp16.h>
#include <mma.h>
#include <cstdint>

using namespace nvcuda;

#define N_TOK 4096
#define DIM   1024
#define NEXP  8
#define HDIM  2048
#define NSLOT 8192
#define PAD   128

// gemm tiling: block 128x128, 4 warps (2x2), warp tile 64x64, BK=32, 3 stages
#define TM 128
#define TN 128
#define BK 32
#define NTH 128
#define LDB 40            // smem row stride in halves (80B)
#define LDC 68            // epilogue fp32 row stride

#define STAGE_H (TM * LDB + TN * LDB)     // halves per stage (10240)
#define SMEM_BYTES (3 * STAGE_H * 2)      // 61440 B; epilogue overlay 34816 B fits

// ---------------- scratch (device globals) ----------------------------------
__device__ __align__(256) __half g_xh[(size_t)N_TOK * DIM];           // x in fp16
__device__ __align__(256) __half g_H [(size_t)(NSLOT + PAD) * HDIM];  // relu out fp16
__device__ __align__(256) __half g_w1h[(size_t)NEXP * HDIM * DIM];
__device__ __align__(256) __half g_w2h[(size_t)NEXP * DIM * HDIM];
__device__ __align__(256) float  g_O [(size_t)NSLOT * DIM];           // per-slot fc2 out
__device__ int   g_expert_tok[NSLOT];
__device__ float g_expert_w[NSLOT];
__device__ int   g_tok_slot[N_TOK * 2];
__device__ int   g_tok_e[N_TOK * 2];
__device__ float g_tok_w[N_TOK * 2];
__device__ int   g_counts[NEXP];
__device__ int   g_cursor[NEXP];
__device__ int   g_offsets[NEXP + 1];
__device__ float g_colsum[NEXP];
__device__ int   g_top1[NEXP];
__device__ int   g_nt;

// ---------------- helpers ---------------------------------------------------
__device__ __forceinline__ uint32_t smem_u32(const void* p) {
    return (uint32_t)__cvta_generic_to_shared(p);
}
__device__ __forceinline__ void cp_async16(uint32_t dst, const void* src) {
    asm volatile("cp.async.cg.shared.global [%0], [%1], 16;\n" :: "r"(dst), "l"(src));
}
__device__ __forceinline__ void cp_commit() {
    asm volatile("cp.async.commit_group;\n" ::: "memory");
}
template<int N> __device__ __forceinline__ void cp_wait() {
    asm volatile("cp.async.wait_group %0;\n" :: "n"(N) : "memory");
}

// ---------------- init -------------------------------------------------------
__global__ void init_kernel() {
    int t = threadIdx.x;
    if (t < NEXP) { g_counts[t] = 0; g_cursor[t] = 0; g_colsum[t] = 0.f; g_top1[t] = 0; }
    if (t == 0) g_nt = 0;
}

// ---------------- gate (fused with x -> fp16 conversion) --------------------
__global__ __launch_bounds__(256) void gate_kernel(
        const float* __restrict__ x,
        const unsigned char* __restrict__ pm,
        const float* __restrict__ gw,
        float* __restrict__ gate_out) {
    __shared__ float gw_s[NEXP * DIM];   // 32 KB

    const int tid = threadIdx.x;
    for (int i = tid; i < NEXP * DIM / 4; i += 256)
        ((float4*)gw_s)[i] = ((const float4*)gw)[i];
    __syncthreads();

    const int wid  = tid >> 5;
    const int lane = tid & 31;
    const int n = blockIdx.x * 8 + wid;
    const float* xr = x + (size_t)n * DIM;

    float acc[NEXP];
#pragma unroll
    for (int e = 0; e < NEXP; e++) acc[e] = 0.f;

#pragma unroll
    for (int i = 0; i < DIM / 128; i++) {          // 8 iters, float4 per lane
        int d = i * 128 + lane * 4;
        float4 v = *(const float4*)&xr[d];
        __half2 h0 = __floats2half2_rn(v.x, v.y);
        __half2 h1 = __floats2half2_rn(v.z, v.w);
        uint2 o;
        o.x = *(uint32_t*)&h0;
        o.y = *(uint32_t*)&h1;
        *(uint2*)&g_xh[(size_t)n * DIM + d] = o;
#pragma unroll
        for (int e = 0; e < NEXP; e++) {
            const float4 w4 = *(const float4*)&gw_s[e * DIM + d];
            acc[e] += v.x * w4.x + v.y * w4.y + v.z * w4.z + v.w * w4.w;
        }
    }
#pragma unroll
    for (int e = 0; e < NEXP; e++) {
#pragma unroll
        for (int o = 16; o > 0; o >>= 1)
            acc[e] += __shfl_xor_sync(0xffffffffu, acc[e], o);
    }

    if (lane == 0) {
        bool masked = (pm[n] != 0);
        float m = acc[0];
#pragma unroll
        for (int e = 1; e < NEXP; e++) m = fmaxf(m, acc[e]);
        float gv[NEXP]; float s = 0.f;
#pragma unroll
        for (int e = 0; e < NEXP; e++) { gv[e] = expf(acc[e] - m); s += gv[e]; }
        float inv = 1.f / s;
#pragma unroll
        for (int e = 0; e < NEXP; e++) {
            gv[e] *= inv;
            if (masked) gv[e] = 0.f;
            gate_out[(size_t)n * NEXP + e] = gv[e];
        }
        int e1 = 0;
#pragma unroll
        for (int e = 1; e < NEXP; e++) if (gv[e] > gv[e1]) e1 = e;
        int e2 = -1;
#pragma unroll
        for (int e = 0; e < NEXP; e++) {
            if (e == e1) continue;
            if (e2 < 0 || gv[e] > gv[e2]) e2 = e;
        }
        float den = gv[e1] + gv[e2];
        if (den == 0.f) den = 1.f;
        g_tok_e[2 * n + 0] = e1;
        g_tok_e[2 * n + 1] = e2;
        g_tok_w[2 * n + 0] = gv[e1] / den;
        g_tok_w[2 * n + 1] = gv[e2] / den;
        atomicAdd(&g_counts[e1], 1);
        atomicAdd(&g_counts[e2], 1);
        if (!masked) { atomicAdd(&g_top1[e1], 1); atomicAdd(&g_nt, 1); }
#pragma unroll
        for (int e = 0; e < NEXP; e++) atomicAdd(&g_colsum[e], gv[e]);
    }
}

__global__ void offsets_kernel() {
    if (threadIdx.x == 0) {
        int off = 0;
        for (int e = 0; e < NEXP; e++) { g_offsets[e] = off; off += g_counts[e]; }
        g_offsets[NEXP] = off;
    }
}

__global__ void scatter_kernel() {
    int n = blockIdx.x * blockDim.x + threadIdx.x;
    if (n >= N_TOK) return;
#pragma unroll
    for (int s = 0; s < 2; s++) {
        int e = g_tok_e[2 * n + s];
        int pos = g_offsets[e] + atomicAdd(&g_cursor[e], 1);
        g_expert_tok[pos] = n;
        g_expert_w[pos]   = g_tok_w[2 * n + s];
        g_tok_slot[2 * n + s] = pos;
    }
}

// ---------------- weight fp32 -> fp16 conversion ----------------------------
template<int WHICH>
__global__ void conv_w_kernel(const float4* __restrict__ src, int n8) {
    uint4* dst = (uint4*)(WHICH == 0 ? g_w1h : g_w2h);
    int stride = gridDim.x * blockDim.x;
    for (int i = blockIdx.x * blockDim.x + threadIdx.x; i < n8; i += stride) {
        float4 v0 = src[2 * i];
        float4 v1 = src[2 * i + 1];
        __half2 h0 = __floats2half2_rn(v0.x, v0.y);
        __half2 h1 = __floats2half2_rn(v0.z, v0.w);
        __half2 h2 = __floats2half2_rn(v1.x, v1.y);
        __half2 h3 = __floats2half2_rn(v1.z, v1.w);
        uint4 o;
        o.x = *(uint32_t*)&h0;
        o.y = *(uint32_t*)&h1;
        o.z = *(uint32_t*)&h2;
        o.w = *(uint32_t*)&h3;
        dst[i] = o;
    }
}

// ---------------- grouped GEMM (fp16 wmma, 64x64 warp tile, 3-stage) --------
// MODE 0: g_H = half(relu(Xg @ w1h^T + b1))    KTOT=DIM,  NCOLS=HDIM  (A = gathered g_xh)
// MODE 1: g_O[slot] = w * (g_H @ w2h^T + b2)   KTOT=HDIM, NCOLS=DIM   (A = g_H)
template<int KTOT, int MODE>
__global__ __launch_bounds__(NTH, 2) void gemm_kernel(const float* __restrict__ bias) {
    const int e = blockIdx.z;
    const int off = g_offsets[e];
    const int cnt = g_offsets[e + 1] - off;
    const int row0 = blockIdx.y * TM;
    if (row0 >= cnt) return;
    const int n0 = blockIdx.x * TN;
    const int NCOLS = (MODE == 0) ? HDIM : DIM;

    extern __shared__ __align__(16) __half sh[];

    const int tid  = threadIdx.x;
    const int warp = tid >> 5;
    const int wm   = warp >> 1;          // 0..1 : 64-row strip
    const int wn   = warp & 1;           // 0..1 : 64-col strip

    const __half* Bbase = (MODE == 0) ? g_w1h : g_w2h;

    const __half* a_src[4];
    uint32_t a_off[4];
    const __half* b_src[4];
    uint32_t b_off[4];
#pragma unroll
    for (int i = 0; i < 4; i++) {
        int cid = tid + i * NTH;         // 0..511
        int r   = cid >> 2;              // 0..127
        int c8  = (cid & 3) * 8;         // 0,8,16,24 halves
        int slot = off + row0 + r;
        if (slot > NSLOT - 1) slot = NSLOT - 1;
        if (MODE == 0) {
            int tok = g_expert_tok[slot];
            a_src[i] = g_xh + (size_t)tok * DIM + c8;
        } else {
            a_src[i] = g_H + (size_t)slot * HDIM + c8;
        }
        a_off[i] = (uint32_t)((r * LDB + c8) * 2);
        b_src[i] = Bbase + (size_t)(e * NCOLS + n0 + r) * KTOT + c8;
        b_off[i] = (uint32_t)((TM * LDB + r * LDB + c8) * 2);
    }
    const uint32_t sbase = smem_u32(sh);
    const uint32_t STAGE_B = STAGE_H * 2;

    wmma::fragment<wmma::accumulator, 16, 16, 16, float> acc[4][4];
#pragma unroll
    for (int i = 0; i < 4; i++)
#pragma unroll
        for (int j = 0; j < 4; j++) wmma::fill_fragment(acc[i][j], 0.f);

    const int T = KTOT / BK;

#pragma unroll
    for (int s = 0; s < 2; s++) {
#pragma unroll
        for (int i = 0; i < 4; i++) {
            cp_async16(sbase + s * STAGE_B + a_off[i], a_src[i] + (size_t)s * BK);
            cp_async16(sbase + s * STAGE_B + b_off[i], b_src[i] + (size_t)s * BK);
        }
        cp_commit();
    }

    int buf = 0;
    for (int t = 0; t < T; t++) {
        if (t < T - 1) cp_wait<1>(); else cp_wait<0>();
        __syncthreads();

        if (t + 2 < T) {
            int pb = (buf + 2 >= 3) ? buf - 1 : buf + 2;
            uint32_t pbb = sbase + pb * STAGE_B;
#pragma unroll
            for (int i = 0; i < 4; i++) {
                cp_async16(pbb + a_off[i], a_src[i] + (size_t)(t + 2) * BK);
                cp_async16(pbb + b_off[i], b_src[i] + (size_t)(t + 2) * BK);
            }
            cp_commit();
        }

        const __half* As = sh + (size_t)buf * STAGE_H;
        const __half* Bs = As + TM * LDB;
#pragma unroll
        for (int kk = 0; kk < BK; kk += 16) {
            wmma::fragment<wmma::matrix_a, 16, 16, 16, half, wmma::row_major> af[4];
            wmma::fragment<wmma::matrix_b, 16, 16, 16, half, wmma::col_major> bf[4];
#pragma unroll
            for (int i = 0; i < 4; i++)
                wmma::load_matrix_sync(af[i], &As[(wm * 64 + i * 16) * LDB + kk], LDB);
#pragma unroll
            for (int j = 0; j < 4; j++)
                wmma::load_matrix_sync(bf[j], &Bs[(wn * 64 + j * 16) * LDB + kk], LDB);
#pragma unroll
            for (int i = 0; i < 4; i++)
#pragma unroll
                for (int j = 0; j < 4; j++)
                    wmma::mma_sync(acc[i][j], af[i], bf[j], acc[i][j]);
        }
        buf = (buf + 1 >= 3) ? 0 : buf + 1;
    }
    __syncthreads();

    float* Cs = (float*)sh;
#pragma unroll
    for (int p = 0; p < 2; p++) {
        if (wn == p) {
#pragma unroll
            for (int i = 0; i < 4; i++)
#pragma unroll
                for (int j = 0; j < 4; j++)
                    wmma::store_matrix_sync(&Cs[(wm * 64 + i * 16) * LDC + j * 16],
                                            acc[i][j], LDC, wmma::mem_row_major);
        }
        __syncthreads();

#pragma unroll
        for (int i = 0; i < 16; i++) {
            int idx4 = tid + i * NTH;
            int r    = idx4 >> 4;
            int c4   = (idx4 & 15) * 4;
            if (row0 + r < cnt) {
                int slot = off + row0 + r;
                int col  = n0 + p * 64 + c4;
                float4 v = *(const float4*)&Cs[r * LDC + c4];
                const float4 bv = *(const float4*)&bias[e * NCOLS + col];
                if (MODE == 0) {
                    __half2 h0 = __floats2half2_rn(fmaxf(v.x + bv.x, 0.f),
                                                   fmaxf(v.y + bv.y, 0.f));
                    __half2 h1 = __floats2half2_rn(fmaxf(v.z + bv.z, 0.f),
                                                   fmaxf(v.w + bv.w, 0.f));
                    uint2 o;
                    o.x = *(uint32_t*)&h0;
                    o.y = *(uint32_t*)&h1;
                    *(uint2*)&g_H[(size_t)slot * HDIM + col] = o;
                } else {
                    float w = g_expert_w[slot];
                    float4 o;
                    o.x = (v.x + bv.x) * w;
                    o.y = (v.y + bv.y) * w;
                    o.z = (v.z + bv.z) * w;
                    o.w = (v.w + bv.w) * w;
                    *(float4*)&g_O[(size_t)slot * DIM + col] = o;
                }
            }
        }
        __syncthreads();
    }
}

// ---------------- combine (+ lb_loss on block 0) -----------------------------
__global__ void combine_kernel(float* __restrict__ out, float* __restrict__ loss_out) {
    int n  = blockIdx.x;
    int c4 = threadIdx.x;
    if (n == 0 && c4 == 0) {
        float nt = (float)g_nt;
        float s = 0.f;
        for (int e = 0; e < NEXP; e++)
            s += ((float)g_top1[e] / nt) * (g_colsum[e] / nt);
        *loss_out = (float)NEXP * s;
    }
    int s0 = g_tok_slot[2 * n + 0];
    int s1 = g_tok_slot[2 * n + 1];
    float4 a = ((const float4*)(g_O + (size_t)s0 * DIM))[c4];
    float4 b = ((const float4*)(g_O + (size_t)s1 * DIM))[c4];
    float4 o;
    o.x = a.x + b.x; o.y = a.y + b.y; o.z = a.z + b.z; o.w = a.w + b.w;
    ((float4*)(out + (size_t)n * DIM))[c4] = o;
}

// ---------------- launch -----------------------------------------------------
extern "C" void kernel_launch(void* const* d_in, const int* in_sizes, int n_in,
                              void* d_out, int out_size) {
    const float*         x      = (const float*)d_in[0];
    const unsigned char* pm     = (const unsigned char*)d_in[1];
    const float*         gate_w = (const float*)d_in[2];
    const float*         fc1_w  = (const float*)d_in[3];
    const float*         fc1_b  = (const float*)d_in[4];
    const float*         fc2_w  = (const float*)d_in[5];
    const float*         fc2_b  = (const float*)d_in[6];
    (void)in_sizes; (void)n_in; (void)out_size;

    float* out      = (float*)d_out;
    float* gate_out = out + (size_t)N_TOK * DIM;
    float* loss_out = gate_out + (size_t)N_TOK * NEXP;

    // one-time host-side resources (no device memory involved)
    static cudaStream_t s1 = nullptr;
    static cudaEvent_t evFork = nullptr, evW0 = nullptr, evW1 = nullptr;
    if (s1 == nullptr) {
        cudaStreamCreateWithFlags(&s1, cudaStreamNonBlocking);
        cudaEventCreateWithFlags(&evFork, cudaEventDisableTiming);
        cudaEventCreateWithFlags(&evW0, cudaEventDisableTiming);
        cudaEventCreateWithFlags(&evW1, cudaEventDisableTiming);
        cudaFuncSetAttribute(gemm_kernel<DIM, 0>,
                             cudaFuncAttributeMaxDynamicSharedMemorySize, SMEM_BYTES);
        cudaFuncSetAttribute(gemm_kernel<HDIM, 1>,
                             cudaFuncAttributeMaxDynamicSharedMemorySize, SMEM_BYTES);
    }

    // fork: weight conversion on s1, independent of routing path
    cudaEventRecord(evFork, 0);
    cudaStreamWaitEvent(s1, evFork, 0);
    conv_w_kernel<0><<<2048, 256, 0, s1>>>((const float4*)fc1_w, NEXP * HDIM * DIM / 8);
    cudaEventRecord(evW0, s1);
    conv_w_kernel<1><<<2048, 256, 0, s1>>>((const float4*)fc2_w, NEXP * DIM * HDIM / 8);
    cudaEventRecord(evW1, s1);

    // main path
    init_kernel<<<1, 32>>>();
    gate_kernel<<<N_TOK / 8, 256>>>(x, pm, gate_w, gate_out);
    offsets_kernel<<<1, 32>>>();
    scatter_kernel<<<N_TOK / 256, 256>>>();

    cudaStreamWaitEvent(0, evW0, 0);     // join: GEMM1 needs w1h
    gemm_kernel<DIM, 0><<<dim3(HDIM / TN, NSLOT / TM, NEXP), NTH, SMEM_BYTES>>>(fc1_b);
    cudaStreamWaitEvent(0, evW1, 0);     // join: GEMM2 needs w2h
    gemm_kernel<HDIM, 1><<<dim3(DIM / TN, NSLOT / TM, NEXP), NTH, SMEM_BYTES>>>(fc2_b);
    combine_kernel<<<N_TOK, DIM / 4>>>(out, loss_out);
}